// round 5
// baseline (speedup 1.0000x reference)
#include <cuda_runtime.h>
#include <cuda_bf16.h>
#include <mma.h>
#include <math.h>
#include <stdint.h>

using namespace nvcuda;

#define B 64
#define T 512
#define D 1024
#define RBLK 64           // recurrence grid (D/16), all co-resident

// ---------------- wx GEMM config (K-concat hi/lo trick, K'=3072) ----------------
#define KK 3072
#define BM 128
#define BN 128
#define BK 32
#define NK (KK / BK)
#define LDT 40
#define STAGE_A (BM * LDT * 2)
#define AB_STAGES 3
#define SMEM_B_OFF (AB_STAGES * STAGE_A)
#define SMEM_BIAS_OFF (2 * AB_STAGES * STAGE_A)
#define GEMM_SMEM (SMEM_BIAS_OFF + 16 * BN * 4)

// ---------------- recurrence smem config ----------------
#define HLD 264                              // padded k-stride for h smem (bf16 elems)
#define ULD 1032                             // padded k-stride for U smem
#define U_ELEMS (16 * ULD)                   // one U matrix (hi or lo)
#define H_ELEMS (64 * HLD)                   // one h chunk matrix
#define RNN_SMEM (2*U_ELEMS*2 + 4*H_ELEMS*2 + 8*256*4)   // 66048+135168+8192 = 209408

// ---------------- scratch ----------------
__device__ float g_dummy;                              // (keep linker happy)
__device__ unsigned g_ctr;                             // grid-barrier counter
__device__ __nv_bfloat16 g_xs[(size_t)B * T * KK];     // x split K-concat [hi|lo|hi]
__device__ __nv_bfloat16 g_ws[(size_t)D * KK];         // W split K-concat [hi|hi|lo]
__device__ __nv_bfloat16 g_hhi[2][B * D];              // h hi, double buffered
__device__ __nv_bfloat16 g_hlo[2][B * D];              // h lo
__device__ __nv_bfloat16 g_uhi[D * D];                 // U hi, row-major [n][k]
__device__ __nv_bfloat16 g_ulo[D * D];                 // U lo

// ---------------- helpers ----------------
__device__ __forceinline__ uint32_t smem_u32(const void* p) {
    uint32_t a;
    asm("{ .reg .u64 t; cvta.to.shared.u64 t, %1; cvt.u32.u64 %0, t; }" : "=r"(a) : "l"(p));
    return a;
}
__device__ __forceinline__ void cp_async16(uint32_t dst, const void* src) {
    asm volatile("cp.async.cg.shared.global [%0], [%1], 16;" :: "r"(dst), "l"(src) : "memory");
}
#define CP_COMMIT() asm volatile("cp.async.commit_group;" ::: "memory")

// ---------------- init ----------------
__global__ void zero_h0() {
    int i = blockIdx.x * blockDim.x + threadIdx.x;
    if (i < B * D) {
        g_hhi[0][i] = __nv_bfloat16(0.f);
        g_hlo[0][i] = __nv_bfloat16(0.f);
    }
    if (i == 0) g_ctr = 0;
}

// ---------------- fp32 -> bf16 splits ----------------
__global__ void split_x(const float* __restrict__ s) {
    size_t i = (size_t)blockIdx.x * blockDim.x + threadIdx.x;
    float4 v = ((const float4*)s)[i];
    size_t e = i * 4;
    size_t m = e >> 10;
    int    k = (int)(e & 1023);
    __nv_bfloat16 hx = __float2bfloat16(v.x), hy = __float2bfloat16(v.y);
    __nv_bfloat16 hz = __float2bfloat16(v.z), hw = __float2bfloat16(v.w);
    __nv_bfloat162 h01(hx, hy), h23(hz, hw);
    __nv_bfloat162 l01(__float2bfloat16(v.x - __bfloat162float(hx)),
                       __float2bfloat16(v.y - __bfloat162float(hy)));
    __nv_bfloat162 l23(__float2bfloat16(v.z - __bfloat162float(hz)),
                       __float2bfloat16(v.w - __bfloat162float(hw)));
    __nv_bfloat16* row = g_xs + m * KK;
    *(__nv_bfloat162*)(row + k)         = h01;  *(__nv_bfloat162*)(row + k + 2)         = h23;
    *(__nv_bfloat162*)(row + D + k)     = l01;  *(__nv_bfloat162*)(row + D + k + 2)     = l23;
    *(__nv_bfloat162*)(row + 2*D + k)   = h01;  *(__nv_bfloat162*)(row + 2*D + k + 2)   = h23;
}
__global__ void split_w(const float* __restrict__ s) {
    size_t i = (size_t)blockIdx.x * blockDim.x + threadIdx.x;
    float4 v = ((const float4*)s)[i];
    size_t e = i * 4;
    size_t n = e >> 10;
    int    k = (int)(e & 1023);
    __nv_bfloat16 hx = __float2bfloat16(v.x), hy = __float2bfloat16(v.y);
    __nv_bfloat16 hz = __float2bfloat16(v.z), hw = __float2bfloat16(v.w);
    __nv_bfloat162 h01(hx, hy), h23(hz, hw);
    __nv_bfloat162 l01(__float2bfloat16(v.x - __bfloat162float(hx)),
                       __float2bfloat16(v.y - __bfloat162float(hy)));
    __nv_bfloat162 l23(__float2bfloat16(v.z - __bfloat162float(hz)),
                       __float2bfloat16(v.w - __bfloat162float(hw)));
    __nv_bfloat16* row = g_ws + n * KK;
    *(__nv_bfloat162*)(row + k)         = h01;  *(__nv_bfloat162*)(row + k + 2)         = h23;
    *(__nv_bfloat162*)(row + D + k)     = h01;  *(__nv_bfloat162*)(row + D + k + 2)     = h23;
    *(__nv_bfloat162*)(row + 2*D + k)   = l01;  *(__nv_bfloat162*)(row + 2*D + k + 2)   = l23;
}
__global__ void split_U(const float* __restrict__ s) {
    size_t i = (size_t)blockIdx.x * blockDim.x + threadIdx.x;
    float4 v = ((const float4*)s)[i];
    __nv_bfloat16 hx = __float2bfloat16(v.x), hy = __float2bfloat16(v.y);
    __nv_bfloat16 hz = __float2bfloat16(v.z), hw = __float2bfloat16(v.w);
    ((__nv_bfloat162*)g_uhi)[2*i]   = __nv_bfloat162(hx, hy);
    ((__nv_bfloat162*)g_uhi)[2*i+1] = __nv_bfloat162(hz, hw);
    ((__nv_bfloat162*)g_ulo)[2*i]   = __nv_bfloat162(__float2bfloat16(v.x - __bfloat162float(hx)),
                                                     __float2bfloat16(v.y - __bfloat162float(hy)));
    ((__nv_bfloat162*)g_ulo)[2*i+1] = __nv_bfloat162(__float2bfloat16(v.z - __bfloat162float(hz)),
                                                     __float2bfloat16(v.w - __bfloat162float(hw)));
}

// ================= wx = x @ W^T + Wb via wmma (unchanged from R4) =================
__device__ __forceinline__ void fill_stage(uint32_t sb, int s, int m0, int n0, int k0, int tid) {
    uint32_t sa = sb + s * STAGE_A;
    uint32_t sbb = sb + SMEM_B_OFF + s * STAGE_A;
    #pragma unroll
    for (int j = 0; j < 2; ++j) {
        int idx = tid + j * 256;
        int r = idx >> 2, c = idx & 3;
        cp_async16(sa + r * (LDT * 2) + c * 16, g_xs + (size_t)(m0 + r) * KK + k0 + c * 8);
    }
    #pragma unroll
    for (int j = 0; j < 2; ++j) {
        int idx = tid + j * 256;
        int r = idx >> 2, c = idx & 3;
        cp_async16(sbb + r * (LDT * 2) + c * 16, g_ws + (size_t)(n0 + r) * KK + k0 + c * 8);
    }
    CP_COMMIT();
}

__global__ void __launch_bounds__(256) gemm_wx_mma(float* __restrict__ out,
                                                   const float* __restrict__ Wb) {
    extern __shared__ char smem[];
    uint32_t sb = smem_u32(smem);
    float* biasT = (float*)(smem + SMEM_BIAS_OFF);
    const int tid = threadIdx.x, warp = tid >> 5;
    const int wm = warp & 3, wn = warp >> 2;
    const int n0 = blockIdx.x * BN, m0 = blockIdx.y * BM;

    for (int i = tid; i < 16 * BN; i += 256) biasT[i] = Wb[n0 + (i & (BN - 1))];
    __syncthreads();

    wmma::fragment<wmma::accumulator, 16, 16, 16, float> c[2][4];
    #pragma unroll
    for (int i = 0; i < 2; ++i)
        #pragma unroll
        for (int j = 0; j < 4; ++j)
            wmma::load_matrix_sync(c[i][j], biasT + wn * 64 + j * 16, BN, wmma::mem_row_major);

    fill_stage(sb, 0, m0, n0, 0, tid);
    fill_stage(sb, 1, m0, n0, BK, tid);

    int rs = 0, ws = 2;
    for (int ks = 0; ks < NK; ++ks) {
        asm volatile("cp.async.wait_group 1;" ::: "memory");
        __syncthreads();

        const __nv_bfloat16* As = (const __nv_bfloat16*)(smem + rs * STAGE_A);
        const __nv_bfloat16* Bs = (const __nv_bfloat16*)(smem + SMEM_B_OFF + rs * STAGE_A);
        #pragma unroll
        for (int kk = 0; kk < 2; ++kk) {
            wmma::fragment<wmma::matrix_a, 16, 16, 16, __nv_bfloat16, wmma::row_major> a[2];
            wmma::fragment<wmma::matrix_b, 16, 16, 16, __nv_bfloat16, wmma::col_major> b[4];
            #pragma unroll
            for (int i = 0; i < 2; ++i)
                wmma::load_matrix_sync(a[i], As + (wm * 32 + i * 16) * LDT + kk * 16, LDT);
            #pragma unroll
            for (int j = 0; j < 4; ++j)
                wmma::load_matrix_sync(b[j], Bs + (wn * 64 + j * 16) * LDT + kk * 16, LDT);
            #pragma unroll
            for (int i = 0; i < 2; ++i)
                #pragma unroll
                for (int j = 0; j < 4; ++j)
                    wmma::mma_sync(c[i][j], a[i], b[j], c[i][j]);
        }

        if (ks + 2 < NK) fill_stage(sb, ws, m0, n0, (ks + 2) * BK, tid);
        else CP_COMMIT();
        rs = (rs == 2) ? 0 : rs + 1;
        ws = (ws == 2) ? 0 : ws + 1;
    }

    #pragma unroll
    for (int i = 0; i < 2; ++i)
        #pragma unroll
        for (int j = 0; j < 4; ++j)
            wmma::store_matrix_sync(out + (size_t)(m0 + wm * 32 + i * 16) * D + n0 + wn * 64 + j * 16,
                                    c[i][j], D, wmma::mem_row_major);
}

// ================= persistent HMMA recurrence =================
// 64 blocks x 256 threads. Block owns 16 n-columns; its U slice (hi/lo bf16)
// lives in SMEM for all 512 steps. h is bf16 hi/lo in global (double-buffered),
// streamed per step in 4 K-chunks of 256 via cp.async double buffer.
// Warps: 4(M=16-row slices) x 2(K halves). 3 products -> one fp32 accumulator.
__global__ void __launch_bounds__(256, 1) rnn_mma(float* __restrict__ out,
                                                  const float* __restrict__ Ub,
                                                  const float* __restrict__ bias) {
    extern __shared__ char sm[];
    __nv_bfloat16* s_uhi = (__nv_bfloat16*)sm;             // [16][ULD]
    __nv_bfloat16* s_ulo = s_uhi + U_ELEMS;                // [16][ULD]
    __nv_bfloat16* s_h   = s_ulo + U_ELEMS;                // [2 buf][hi,lo][64][HLD]
    float* s_red = (float*)(s_h + 4 * H_ELEMS);            // [8][16][16]

    const int tid = threadIdx.x, warp = tid >> 5;
    const int wm = warp & 3, wk = warp >> 2;
    const int n0 = blockIdx.x * 16;

    // ---- stage U slice (resident for whole kernel) ----
    {
        uint32_t duh = smem_u32(s_uhi), dul = smem_u32(s_ulo);
        for (int i = tid; i < 16 * 128; i += 256) {       // 16 rows x 128 16B-chunks
            int r = i >> 7, c = i & 127;
            cp_async16(duh + (r * ULD) * 2 + c * 16, g_uhi + (size_t)(n0 + r) * D + c * 8);
            cp_async16(dul + (r * ULD) * 2 + c * 16, g_ulo + (size_t)(n0 + r) * D + c * 8);
        }
        CP_COMMIT();
        asm volatile("cp.async.wait_group 0;" ::: "memory");
        __syncthreads();
    }

    // ---- epilogue constants: thread covers 4 outputs (b, n0+nl..nl+3) ----
    const int eb  = tid >> 2;          // batch 0..63
    const int enl = (tid & 3) * 4;     // n_local 0,4,8,12
    float4 cconst;
    {
        const float4 u4 = *(const float4*)(Ub + n0 + enl);
        const float4 b4 = *(const float4*)(bias + n0 + enl);
        cconst = make_float4(u4.x + b4.x, u4.y + b4.y, u4.z + b4.z, u4.w + b4.w);
    }
    const size_t obase = (size_t)eb * (T * D) + n0 + enl;
    const int    hbase = eb * D + n0 + enl;

    const uint32_t sh32 = smem_u32(s_h);

    for (int t = 0; t < T; ++t) {
        const __nv_bfloat16* Hhi = g_hhi[t & 1];
        const __nv_bfloat16* Hlo = g_hlo[t & 1];

        // stage(c): copy h chunk [64 x 256] hi+lo into buffer c&1
        #define STAGE_H(c) do {                                                       \
            uint32_t dh = sh32 + (((c) & 1) * 2) * H_ELEMS * 2;                       \
            uint32_t dl = dh + H_ELEMS * 2;                                           \
            int k0 = (c) * 256;                                                       \
            for (int i = tid; i < 64 * 32; i += 256) {                                \
                int r = i >> 5, cc = i & 31;                                          \
                cp_async16(dh + r * (HLD * 2) + cc * 16, Hhi + r * D + k0 + cc * 8);  \
                cp_async16(dl + r * (HLD * 2) + cc * 16, Hlo + r * D + k0 + cc * 8);  \
            }                                                                         \
            CP_COMMIT();                                                              \
        } while (0)

        STAGE_H(0);
        STAGE_H(1);

        wmma::fragment<wmma::accumulator, 16, 16, 16, float> acc;
        wmma::fill_fragment(acc, 0.f);

        #pragma unroll
        for (int c = 0; c < 4; ++c) {
            if (c < 3) asm volatile("cp.async.wait_group 1;" ::: "memory");
            else       asm volatile("cp.async.wait_group 0;" ::: "memory");
            __syncthreads();

            const __nv_bfloat16* hb_hi = s_h + ((c & 1) * 2) * H_ELEMS;
            const __nv_bfloat16* hb_lo = hb_hi + H_ELEMS;
            #pragma unroll
            for (int ks = 0; ks < 8; ++ks) {
                const int kl = wk * 128 + ks * 16;      // k within chunk
                const int kg = c * 256 + kl;            // k within row (U)
                wmma::fragment<wmma::matrix_a, 16, 16, 16, __nv_bfloat16, wmma::row_major> ah, al;
                wmma::fragment<wmma::matrix_b, 16, 16, 16, __nv_bfloat16, wmma::col_major> bh, bl;
                wmma::load_matrix_sync(ah, hb_hi + wm * 16 * HLD + kl, HLD);
                wmma::load_matrix_sync(al, hb_lo + wm * 16 * HLD + kl, HLD);
                wmma::load_matrix_sync(bh, s_uhi + kg, ULD);
                wmma::load_matrix_sync(bl, s_ulo + kg, ULD);
                wmma::mma_sync(acc, ah, bh, acc);
                wmma::mma_sync(acc, al, bh, acc);
                wmma::mma_sync(acc, ah, bl, acc);
            }
            __syncthreads();             // all warps done with buffer before refill
            if (c + 2 < 4) STAGE_H(c + 2);
        }

        // ---- 2-way K reduction + fused epilogue ----
        wmma::store_matrix_sync(s_red + warp * 256, acc, 16, wmma::mem_row_major);
        __syncthreads();

        {
            const int slot = eb >> 4;            // which wm covers this batch row
            const int r    = eb & 15;
            const float* p0 = s_red + slot * 256 + r * 16 + enl;
            const float* p1 = p0 + 4 * 256;
            float4 wx = *(const float4*)(out + obase + (size_t)t * D);
            float4 z;
            z.x = tanhf(wx.x + p0[0] + p1[0] + cconst.x);
            z.y = tanhf(wx.y + p0[1] + p1[1] + cconst.y);
            z.z = tanhf(wx.z + p0[2] + p1[2] + cconst.z);
            z.w = tanhf(wx.w + p0[3] + p1[3] + cconst.w);
            *(float4*)(out + obase + (size_t)t * D) = z;

            // split new h to bf16 hi/lo for next step
            __nv_bfloat16 hx = __float2bfloat16(z.x), hy = __float2bfloat16(z.y);
            __nv_bfloat16 hz = __float2bfloat16(z.z), hw = __float2bfloat16(z.w);
            __nv_bfloat16* dh = g_hhi[(t + 1) & 1] + hbase;
            __nv_bfloat16* dl = g_hlo[(t + 1) & 1] + hbase;
            *(__nv_bfloat162*)(dh)     = __nv_bfloat162(hx, hy);
            *(__nv_bfloat162*)(dh + 2) = __nv_bfloat162(hz, hw);
            *(__nv_bfloat162*)(dl)     = __nv_bfloat162(__float2bfloat16(z.x - __bfloat162float(hx)),
                                                        __float2bfloat16(z.y - __bfloat162float(hy)));
            *(__nv_bfloat162*)(dl + 2) = __nv_bfloat162(__float2bfloat16(z.z - __bfloat162float(hz)),
                                                        __float2bfloat16(z.w - __bfloat162float(hw)));
        }

        // ---- grid barrier ----
        __threadfence();
        __syncthreads();
        if (tid == 0) {
            atomicAdd(&g_ctr, 1u);
            unsigned target = (unsigned)(t + 1) * RBLK;
            while (*(volatile unsigned*)&g_ctr < target) { }
            __threadfence();
        }
        __syncthreads();
        #undef STAGE_H
    }
}

// ---------------- copy final hidden state into hx region ----------------
__global__ void copy_hx(float* __restrict__ out) {
    int i = blockIdx.x * blockDim.x + threadIdx.x;
    if (i < B * D) {
        int b = i >> 10, n = i & (D - 1);
        out[(size_t)B * T * D + i] = out[(size_t)b * T * D + (size_t)(T - 1) * D + n];
    }
}

extern "C" void kernel_launch(void* const* d_in, const int* in_sizes, int n_in,
                              void* d_out, int out_size) {
    const float* x    = (const float*)d_in[0];
    const float* Ww   = (const float*)d_in[1];
    const float* Wb   = (const float*)d_in[2];
    const float* Uw   = (const float*)d_in[3];
    const float* Ub   = (const float*)d_in[4];
    const float* bias = (const float*)d_in[5];
    float* out = (float*)d_out;

    cudaFuncSetAttribute(gemm_wx_mma, cudaFuncAttributeMaxDynamicSharedMemorySize, GEMM_SMEM);
    cudaFuncSetAttribute(rnn_mma,     cudaFuncAttributeMaxDynamicSharedMemorySize, RNN_SMEM);

    zero_h0<<<(B * D + 255) / 256, 256>>>();
    split_x<<<((size_t)B * T * D / 4) / 256, 256>>>(x);
    split_w<<<(D * D / 4) / 256, 256>>>(Ww);
    split_U<<<(D * D / 4) / 256, 256>>>(Uw);
    gemm_wx_mma<<<dim3(D / BN, (B * T) / BM), 256, GEMM_SMEM>>>(out, Wb);
    rnn_mma<<<RBLK, 256, RNN_SMEM>>>(out, Ub, bias);
    copy_hx<<<(B * D + 255) / 256, 256>>>(out);
}

// round 7
// speedup vs baseline: 1.5690x; 1.5690x over previous
#include <cuda_runtime.h>
#include <cuda_bf16.h>
#include <mma.h>
#include <math.h>
#include <stdint.h>

using namespace nvcuda;

#define B 64
#define T 512
#define D 1024
#define RBLK 128          // recurrence grid: 32 n-splits x 4 b-splits

// ---------------- wx GEMM config (K-concat hi/lo trick, K'=3072) ----------------
#define KK 3072
#define BM 128
#define BN 128
#define BK 32
#define NK (KK / BK)
#define LDT 40
#define STAGE_A (BM * LDT * 2)
#define AB_STAGES 3
#define SMEM_B_OFF (AB_STAGES * STAGE_A)
#define SMEM_BIAS_OFF (2 * AB_STAGES * STAGE_A)
#define GEMM_SMEM (SMEM_BIAS_OFF + 16 * BN * 4)

// ---------------- recurrence smem config ----------------
#define ULD 1032                               // padded k-stride (bf16 elems)
#define U_ELEMS (32 * ULD)                     // 32 n-rows x 1032
#define H_ELEMS (16 * ULD)                     // 16 b-rows x 1032
// layout: s_uhi | s_ulo | s_hhi | s_hlo | s_red
#define RNN_SMEM ((2 * U_ELEMS + 2 * H_ELEMS) * 2 + 8 * 512 * 4)   // 214528 B

// ---------------- scratch ----------------
__device__ unsigned g_ctr;                             // grid-barrier counter
__device__ __nv_bfloat16 g_xs[(size_t)B * T * KK];     // x split K-concat [hi|lo|hi]
__device__ __nv_bfloat16 g_ws[(size_t)D * KK];         // W split K-concat [hi|hi|lo]
__device__ __nv_bfloat16 g_hhi[2][B * D];              // h hi, double buffered
__device__ __nv_bfloat16 g_hlo[2][B * D];              // h lo
__device__ __nv_bfloat16 g_uhi[D * D];                 // U hi, row-major [n][k]
__device__ __nv_bfloat16 g_ulo[D * D];                 // U lo

// ---------------- helpers ----------------
__device__ __forceinline__ uint32_t smem_u32(const void* p) {
    uint32_t a;
    asm("{ .reg .u64 t; cvta.to.shared.u64 t, %1; cvt.u32.u64 %0, t; }" : "=r"(a) : "l"(p));
    return a;
}
__device__ __forceinline__ void cp_async16(uint32_t dst, const void* src) {
    asm volatile("cp.async.cg.shared.global [%0], [%1], 16;" :: "r"(dst), "l"(src) : "memory");
}
#define CP_COMMIT() asm volatile("cp.async.commit_group;" ::: "memory")

// ---------------- init ----------------
__global__ void zero_h0() {
    int i = blockIdx.x * blockDim.x + threadIdx.x;
    if (i < B * D) {
        g_hhi[0][i] = __nv_bfloat16(0.f);
        g_hlo[0][i] = __nv_bfloat16(0.f);
    }
    if (i == 0) g_ctr = 0;
}

// ---------------- fp32 -> bf16 splits ----------------
__global__ void split_x(const float* __restrict__ s) {
    size_t i = (size_t)blockIdx.x * blockDim.x + threadIdx.x;
    float4 v = ((const float4*)s)[i];
    size_t e = i * 4;
    size_t m = e >> 10;
    int    k = (int)(e & 1023);
    __nv_bfloat16 hx = __float2bfloat16(v.x), hy = __float2bfloat16(v.y);
    __nv_bfloat16 hz = __float2bfloat16(v.z), hw = __float2bfloat16(v.w);
    __nv_bfloat162 h01(hx, hy), h23(hz, hw);
    __nv_bfloat162 l01(__float2bfloat16(v.x - __bfloat162float(hx)),
                       __float2bfloat16(v.y - __bfloat162float(hy)));
    __nv_bfloat162 l23(__float2bfloat16(v.z - __bfloat162float(hz)),
                       __float2bfloat16(v.w - __bfloat162float(hw)));
    __nv_bfloat16* row = g_xs + m * KK;
    *(__nv_bfloat162*)(row + k)       = h01;  *(__nv_bfloat162*)(row + k + 2)       = h23;
    *(__nv_bfloat162*)(row + D + k)   = l01;  *(__nv_bfloat162*)(row + D + k + 2)   = l23;
    *(__nv_bfloat162*)(row + 2*D + k) = h01;  *(__nv_bfloat162*)(row + 2*D + k + 2) = h23;
}
__global__ void split_w(const float* __restrict__ s) {
    size_t i = (size_t)blockIdx.x * blockDim.x + threadIdx.x;
    float4 v = ((const float4*)s)[i];
    size_t e = i * 4;
    size_t n = e >> 10;
    int    k = (int)(e & 1023);
    __nv_bfloat16 hx = __float2bfloat16(v.x), hy = __float2bfloat16(v.y);
    __nv_bfloat16 hz = __float2bfloat16(v.z), hw = __float2bfloat16(v.w);
    __nv_bfloat162 h01(hx, hy), h23(hz, hw);
    __nv_bfloat162 l01(__float2bfloat16(v.x - __bfloat162float(hx)),
                       __float2bfloat16(v.y - __bfloat162float(hy)));
    __nv_bfloat162 l23(__float2bfloat16(v.z - __bfloat162float(hz)),
                       __float2bfloat16(v.w - __bfloat162float(hw)));
    __nv_bfloat16* row = g_ws + n * KK;
    *(__nv_bfloat162*)(row + k)       = h01;  *(__nv_bfloat162*)(row + k + 2)       = h23;
    *(__nv_bfloat162*)(row + D + k)   = h01;  *(__nv_bfloat162*)(row + D + k + 2)   = h23;
    *(__nv_bfloat162*)(row + 2*D + k) = l01;  *(__nv_bfloat162*)(row + 2*D + k + 2) = l23;
}
__global__ void split_U(const float* __restrict__ s) {
    size_t i = (size_t)blockIdx.x * blockDim.x + threadIdx.x;
    float4 v = ((const float4*)s)[i];
    __nv_bfloat16 hx = __float2bfloat16(v.x), hy = __float2bfloat16(v.y);
    __nv_bfloat16 hz = __float2bfloat16(v.z), hw = __float2bfloat16(v.w);
    ((__nv_bfloat162*)g_uhi)[2*i]   = __nv_bfloat162(hx, hy);
    ((__nv_bfloat162*)g_uhi)[2*i+1] = __nv_bfloat162(hz, hw);
    ((__nv_bfloat162*)g_ulo)[2*i]   = __nv_bfloat162(__float2bfloat16(v.x - __bfloat162float(hx)),
                                                     __float2bfloat16(v.y - __bfloat162float(hy)));
    ((__nv_bfloat162*)g_ulo)[2*i+1] = __nv_bfloat162(__float2bfloat16(v.z - __bfloat162float(hz)),
                                                     __float2bfloat16(v.w - __bfloat162float(hw)));
}

// ================= wx = x @ W^T + Wb via wmma (unchanged, proven) =================
__device__ __forceinline__ void fill_stage(uint32_t sb, int s, int m0, int n0, int k0, int tid) {
    uint32_t sa = sb + s * STAGE_A;
    uint32_t sbb = sb + SMEM_B_OFF + s * STAGE_A;
    #pragma unroll
    for (int j = 0; j < 2; ++j) {
        int idx = tid + j * 256;
        int r = idx >> 2, c = idx & 3;
        cp_async16(sa + r * (LDT * 2) + c * 16, g_xs + (size_t)(m0 + r) * KK + k0 + c * 8);
    }
    #pragma unroll
    for (int j = 0; j < 2; ++j) {
        int idx = tid + j * 256;
        int r = idx >> 2, c = idx & 3;
        cp_async16(sbb + r * (LDT * 2) + c * 16, g_ws + (size_t)(n0 + r) * KK + k0 + c * 8);
    }
    CP_COMMIT();
}

__global__ void __launch_bounds__(256) gemm_wx_mma(float* __restrict__ out,
                                                   const float* __restrict__ Wb) {
    extern __shared__ char smem[];
    uint32_t sb = smem_u32(smem);
    float* biasT = (float*)(smem + SMEM_BIAS_OFF);
    const int tid = threadIdx.x, warp = tid >> 5;
    const int wm = warp & 3, wn = warp >> 2;
    const int n0 = blockIdx.x * BN, m0 = blockIdx.y * BM;

    for (int i = tid; i < 16 * BN; i += 256) biasT[i] = Wb[n0 + (i & (BN - 1))];
    __syncthreads();

    wmma::fragment<wmma::accumulator, 16, 16, 16, float> c[2][4];
    #pragma unroll
    for (int i = 0; i < 2; ++i)
        #pragma unroll
        for (int j = 0; j < 4; ++j)
            wmma::load_matrix_sync(c[i][j], biasT + wn * 64 + j * 16, BN, wmma::mem_row_major);

    fill_stage(sb, 0, m0, n0, 0, tid);
    fill_stage(sb, 1, m0, n0, BK, tid);

    int rs = 0, ws = 2;
    for (int ks = 0; ks < NK; ++ks) {
        asm volatile("cp.async.wait_group 1;" ::: "memory");
        __syncthreads();

        const __nv_bfloat16* As = (const __nv_bfloat16*)(smem + rs * STAGE_A);
        const __nv_bfloat16* Bs = (const __nv_bfloat16*)(smem + SMEM_B_OFF + rs * STAGE_A);
        #pragma unroll
        for (int kk = 0; kk < 2; ++kk) {
            wmma::fragment<wmma::matrix_a, 16, 16, 16, __nv_bfloat16, wmma::row_major> a[2];
            wmma::fragment<wmma::matrix_b, 16, 16, 16, __nv_bfloat16, wmma::col_major> b[4];
            #pragma unroll
            for (int i = 0; i < 2; ++i)
                wmma::load_matrix_sync(a[i], As + (wm * 32 + i * 16) * LDT + kk * 16, LDT);
            #pragma unroll
            for (int j = 0; j < 4; ++j)
                wmma::load_matrix_sync(b[j], Bs + (wn * 64 + j * 16) * LDT + kk * 16, LDT);
            #pragma unroll
            for (int i = 0; i < 2; ++i)
                #pragma unroll
                for (int j = 0; j < 4; ++j)
                    wmma::mma_sync(c[i][j], a[i], b[j], c[i][j]);
        }

        if (ks + 2 < NK) fill_stage(sb, ws, m0, n0, (ks + 2) * BK, tid);
        else CP_COMMIT();
        rs = (rs == 2) ? 0 : rs + 1;
        ws = (ws == 2) ? 0 : ws + 1;
    }

    #pragma unroll
    for (int i = 0; i < 2; ++i)
        #pragma unroll
        for (int j = 0; j < 4; ++j)
            wmma::store_matrix_sync(out + (size_t)(m0 + wm * 32 + i * 16) * D + n0 + wn * 64 + j * 16,
                                    c[i][j], D, wmma::mem_row_major);
}

// ================= persistent HMMA recurrence, (n,b)-partitioned =================
// 128 blocks x 256 threads. Block (ni, bi) owns n-cols [ni*32, +32), batches
// [bi*16, +16). U slice (hi/lo) SMEM-resident for all 512 steps. Per step each
// warp self-stages its own 16(b) x 128(k) hi/lo h slab (cp.async, wait own
// group, __syncwarp) -> 48 wmma -> 8-way smem reduction -> fused epilogue.
// Exactly one __syncthreads per step plus the grid barrier.
__global__ void __launch_bounds__(256, 1) rnn_mma(float* __restrict__ out,
                                                  const float* __restrict__ Ub,
                                                  const float* __restrict__ bias) {
    extern __shared__ char sm[];
    __nv_bfloat16* s_uhi = (__nv_bfloat16*)sm;             // [32][ULD]
    __nv_bfloat16* s_ulo = s_uhi + U_ELEMS;
    __nv_bfloat16* s_hhi = s_ulo + U_ELEMS;                // [16][ULD]
    __nv_bfloat16* s_hlo = s_hhi + H_ELEMS;
    float* s_red = (float*)(s_hlo + H_ELEMS);              // [8 warps][2 nfrag][16][16]

    const int tid = threadIdx.x, warp = tid >> 5, lane = tid & 31;
    const int ni = blockIdx.x >> 2, bi = blockIdx.x & 3;
    const int n0 = ni * 32, b0 = bi * 16;

    // ---- stage U slice once (resident for whole kernel) ----
    // 32 rows x 128 16B-chunks per matrix (FULL 1024-k rows — R6 bug was 64 chunks)
    {
        uint32_t duh = smem_u32(s_uhi), dul = smem_u32(s_ulo);
        for (int i = tid; i < 32 * 128; i += 256) {
            int r = i >> 7, c = i & 127;
            cp_async16(duh + (r * ULD + c * 8) * 2, g_uhi + (size_t)(n0 + r) * D + c * 8);
            cp_async16(dul + (r * ULD + c * 8) * 2, g_ulo + (size_t)(n0 + r) * D + c * 8);
        }
        CP_COMMIT();
        asm volatile("cp.async.wait_group 0;" ::: "memory");
        __syncthreads();
    }

    // ---- per-warp staging geometry: warp owns k-chunk [warp*128, +128) ----
    const int kc0 = warp * 128;
    const uint32_t shh = smem_u32(s_hhi), shl = smem_u32(s_hlo);

    // ---- epilogue constants: thread covers 2 outputs (b, nl), (b, nl+1) ----
    const int eb  = tid >> 4;           // 0..15 local batch
    const int enl = (tid & 15) * 2;     // n_local 0,2,..,30
    float2 cconst;
    {
        cconst.x = Ub[n0 + enl]     + bias[n0 + enl];
        cconst.y = Ub[n0 + enl + 1] + bias[n0 + enl + 1];
    }
    const size_t obase = (size_t)(b0 + eb) * (T * D) + n0 + enl;
    const int    hbase = (b0 + eb) * D + n0 + enl;
    const int    efr   = enl >> 4;          // n fragment (0/1)
    const int    ec    = enl & 15;          // col within fragment (even)

    for (int t = 0; t < T; ++t) {
        const __nv_bfloat16* Hhi = g_hhi[t & 1];
        const __nv_bfloat16* Hlo = g_hlo[t & 1];

        // ---- self-stage this warp's h slab: 16 rows x 128 k, hi+lo ----
        #pragma unroll
        for (int j = 0; j < 8; ++j) {
            int i = lane + j * 32;              // 0..255
            int r = i >> 4, c = i & 15;         // row, 16B-chunk within 128k
            uint32_t off = (r * ULD + kc0 + c * 8) * 2;
            const size_t goff = (size_t)(b0 + r) * D + kc0 + c * 8;
            cp_async16(shh + off, Hhi + goff);
            cp_async16(shl + off, Hlo + goff);
        }
        CP_COMMIT();
        asm volatile("cp.async.wait_group 0;" ::: "memory");
        __syncwarp();

        // ---- compute: M=16(b) x N=32 x K=128, 3 products ----
        wmma::fragment<wmma::accumulator, 16, 16, 16, float> acc[2];
        wmma::fill_fragment(acc[0], 0.f);
        wmma::fill_fragment(acc[1], 0.f);
        #pragma unroll
        for (int ks = 0; ks < 8; ++ks) {
            const int kg = kc0 + ks * 16;
            wmma::fragment<wmma::matrix_a, 16, 16, 16, __nv_bfloat16, wmma::row_major> ah, al;
            wmma::load_matrix_sync(ah, s_hhi + kg, ULD);
            wmma::load_matrix_sync(al, s_hlo + kg, ULD);
            #pragma unroll
            for (int j = 0; j < 2; ++j) {
                wmma::fragment<wmma::matrix_b, 16, 16, 16, __nv_bfloat16, wmma::col_major> bh, bl;
                wmma::load_matrix_sync(bh, s_uhi + (size_t)(j * 16) * ULD + kg, ULD);
                wmma::load_matrix_sync(bl, s_ulo + (size_t)(j * 16) * ULD + kg, ULD);
                wmma::mma_sync(acc[j], ah, bh, acc[j]);
                wmma::mma_sync(acc[j], al, bh, acc[j]);
                wmma::mma_sync(acc[j], ah, bl, acc[j]);
            }
        }
        wmma::store_matrix_sync(s_red + warp * 512,       acc[0], 16, wmma::mem_row_major);
        wmma::store_matrix_sync(s_red + warp * 512 + 256, acc[1], 16, wmma::mem_row_major);
        __syncthreads();

        // ---- 8-way K reduction + fused epilogue (2 outputs/thread) ----
        {
            const float* p = s_red + efr * 256 + eb * 16 + ec;
            float s0 = 0.f, s1 = 0.f;
            #pragma unroll
            for (int w = 0; w < 8; ++w) { s0 += p[w * 512]; s1 += p[w * 512 + 1]; }
            float2 wx = *(const float2*)(out + obase + (size_t)t * D);
            float zx = tanhf(wx.x + s0 + cconst.x);
            float zy = tanhf(wx.y + s1 + cconst.y);
            *(float2*)(out + obase + (size_t)t * D) = make_float2(zx, zy);

            __nv_bfloat16 hx = __float2bfloat16(zx), hy = __float2bfloat16(zy);
            *(__nv_bfloat162*)(g_hhi[(t + 1) & 1] + hbase) = __nv_bfloat162(hx, hy);
            *(__nv_bfloat162*)(g_hlo[(t + 1) & 1] + hbase) =
                __nv_bfloat162(__float2bfloat16(zx - __bfloat162float(hx)),
                               __float2bfloat16(zy - __bfloat162float(hy)));
        }

        // ---- grid barrier ----
        __threadfence();
        __syncthreads();
        if (tid == 0) {
            atomicAdd(&g_ctr, 1u);
            unsigned target = (unsigned)(t + 1) * RBLK;
            while (*(volatile unsigned*)&g_ctr < target) { }
            __threadfence();
        }
        __syncthreads();
    }
}

// ---------------- copy final hidden state into hx region ----------------
__global__ void copy_hx(float* __restrict__ out) {
    int i = blockIdx.x * blockDim.x + threadIdx.x;
    if (i < B * D) {
        int b = i >> 10, n = i & (D - 1);
        out[(size_t)B * T * D + i] = out[(size_t)b * T * D + (size_t)(T - 1) * D + n];
    }
}

extern "C" void kernel_launch(void* const* d_in, const int* in_sizes, int n_in,
                              void* d_out, int out_size) {
    const float* x    = (const float*)d_in[0];
    const float* Ww   = (const float*)d_in[1];
    const float* Wb   = (const float*)d_in[2];
    const float* Uw   = (const float*)d_in[3];
    const float* Ub   = (const float*)d_in[4];
    const float* bias = (const float*)d_in[5];
    float* out = (float*)d_out;

    cudaFuncSetAttribute(gemm_wx_mma, cudaFuncAttributeMaxDynamicSharedMemorySize, GEMM_SMEM);
    cudaFuncSetAttribute(rnn_mma,     cudaFuncAttributeMaxDynamicSharedMemorySize, RNN_SMEM);

    zero_h0<<<(B * D + 255) / 256, 256>>>();
    split_x<<<((size_t)B * T * D / 4) / 256, 256>>>(x);
    split_w<<<(D * D / 4) / 256, 256>>>(Ww);
    split_U<<<(D * D / 4) / 256, 256>>>(Uw);
    gemm_wx_mma<<<dim3(D / BN, (B * T) / BM), 256, GEMM_SMEM>>>(out, Wb);
    rnn_mma<<<RBLK, 256, RNN_SMEM>>>(out, Ub, bias);
    copy_hx<<<(B * D + 255) / 256, 256>>>(out);
}

// round 8
// speedup vs baseline: 1.6917x; 1.0782x over previous
#include <cuda_runtime.h>
#include <cuda_bf16.h>
#include <mma.h>
#include <math.h>
#include <stdint.h>

using namespace nvcuda;

#define B 64
#define T 512
#define D 1024
#define RBLK 128          // recurrence grid: 32 n-splits x 4 b-splits

// ---------------- wx GEMM config (K-concat hi/lo trick, K'=3072) ----------------
#define KK 3072
#define BM 128
#define BN 128
#define BK 32
#define NK (KK / BK)
#define LDT 40
#define STAGE_A (BM * LDT * 2)
#define AB_STAGES 3
#define SMEM_B_OFF (AB_STAGES * STAGE_A)
#define SMEM_BIAS_OFF (2 * AB_STAGES * STAGE_A)
#define GEMM_SMEM (SMEM_BIAS_OFF + 16 * BN * 4)

// ---------------- recurrence smem config ----------------
#define ULD 1032                               // padded k-stride (bf16 elems)
#define U_ELEMS (32 * ULD)                     // 32 n-rows x 1032
#define H_ELEMS (16 * ULD)                     // 16 b-rows x 1032
// layout: s_uhi | s_ulo | s_hhi | s_hlo | s_red | s_wx(2x512 fp32)
#define RNN_SMEM ((2 * U_ELEMS + 2 * H_ELEMS) * 2 + 8 * 512 * 4 + 2 * 512 * 4)  // 218624 B

// ---------------- scratch ----------------
__device__ unsigned g_ctrs[4];                         // per-bi grid-barrier counters
__device__ __nv_bfloat16 g_xs[(size_t)B * T * KK];     // x split K-concat [hi|lo|hi]
__device__ __nv_bfloat16 g_ws[(size_t)D * KK];         // W split K-concat [hi|hi|lo]
__device__ __nv_bfloat16 g_hhi[2][B * D];              // h hi, double buffered
__device__ __nv_bfloat16 g_hlo[2][B * D];              // h lo
__device__ __nv_bfloat16 g_uhi[D * D];                 // U hi, row-major [n][k]
__device__ __nv_bfloat16 g_ulo[D * D];                 // U lo

// ---------------- helpers ----------------
__device__ __forceinline__ uint32_t smem_u32(const void* p) {
    uint32_t a;
    asm("{ .reg .u64 t; cvta.to.shared.u64 t, %1; cvt.u32.u64 %0, t; }" : "=r"(a) : "l"(p));
    return a;
}
__device__ __forceinline__ void cp_async16(uint32_t dst, const void* src) {
    asm volatile("cp.async.cg.shared.global [%0], [%1], 16;" :: "r"(dst), "l"(src) : "memory");
}
#define CP_COMMIT() asm volatile("cp.async.commit_group;" ::: "memory")

// ---------------- init ----------------
__global__ void zero_h0() {
    int i = blockIdx.x * blockDim.x + threadIdx.x;
    if (i < B * D) {
        g_hhi[0][i] = __nv_bfloat16(0.f);
        g_hlo[0][i] = __nv_bfloat16(0.f);
    }
    if (i < 4) g_ctrs[i] = 0;
}

// ---------------- fp32 -> bf16 splits ----------------
__global__ void split_x(const float* __restrict__ s) {
    size_t i = (size_t)blockIdx.x * blockDim.x + threadIdx.x;
    float4 v = ((const float4*)s)[i];
    size_t e = i * 4;
    size_t m = e >> 10;
    int    k = (int)(e & 1023);
    __nv_bfloat16 hx = __float2bfloat16(v.x), hy = __float2bfloat16(v.y);
    __nv_bfloat16 hz = __float2bfloat16(v.z), hw = __float2bfloat16(v.w);
    __nv_bfloat162 h01(hx, hy), h23(hz, hw);
    __nv_bfloat162 l01(__float2bfloat16(v.x - __bfloat162float(hx)),
                       __float2bfloat16(v.y - __bfloat162float(hy)));
    __nv_bfloat162 l23(__float2bfloat16(v.z - __bfloat162float(hz)),
                       __float2bfloat16(v.w - __bfloat162float(hw)));
    __nv_bfloat16* row = g_xs + m * KK;
    *(__nv_bfloat162*)(row + k)       = h01;  *(__nv_bfloat162*)(row + k + 2)       = h23;
    *(__nv_bfloat162*)(row + D + k)   = l01;  *(__nv_bfloat162*)(row + D + k + 2)   = l23;
    *(__nv_bfloat162*)(row + 2*D + k) = h01;  *(__nv_bfloat162*)(row + 2*D + k + 2) = h23;
}
__global__ void split_w(const float* __restrict__ s) {
    size_t i = (size_t)blockIdx.x * blockDim.x + threadIdx.x;
    float4 v = ((const float4*)s)[i];
    size_t e = i * 4;
    size_t n = e >> 10;
    int    k = (int)(e & 1023);
    __nv_bfloat16 hx = __float2bfloat16(v.x), hy = __float2bfloat16(v.y);
    __nv_bfloat16 hz = __float2bfloat16(v.z), hw = __float2bfloat16(v.w);
    __nv_bfloat162 h01(hx, hy), h23(hz, hw);
    __nv_bfloat162 l01(__float2bfloat16(v.x - __bfloat162float(hx)),
                       __float2bfloat16(v.y - __bfloat162float(hy)));
    __nv_bfloat162 l23(__float2bfloat16(v.z - __bfloat162float(hz)),
                       __float2bfloat16(v.w - __bfloat162float(hw)));
    __nv_bfloat16* row = g_ws + n * KK;
    *(__nv_bfloat162*)(row + k)       = h01;  *(__nv_bfloat162*)(row + k + 2)       = h23;
    *(__nv_bfloat162*)(row + D + k)   = h01;  *(__nv_bfloat162*)(row + D + k + 2)   = h23;
    *(__nv_bfloat162*)(row + 2*D + k) = l01;  *(__nv_bfloat162*)(row + 2*D + k + 2) = l23;
}
__global__ void split_U(const float* __restrict__ s) {
    size_t i = (size_t)blockIdx.x * blockDim.x + threadIdx.x;
    float4 v = ((const float4*)s)[i];
    __nv_bfloat16 hx = __float2bfloat16(v.x), hy = __float2bfloat16(v.y);
    __nv_bfloat16 hz = __float2bfloat16(v.z), hw = __float2bfloat16(v.w);
    ((__nv_bfloat162*)g_uhi)[2*i]   = __nv_bfloat162(hx, hy);
    ((__nv_bfloat162*)g_uhi)[2*i+1] = __nv_bfloat162(hz, hw);
    ((__nv_bfloat162*)g_ulo)[2*i]   = __nv_bfloat162(__float2bfloat16(v.x - __bfloat162float(hx)),
                                                     __float2bfloat16(v.y - __bfloat162float(hy)));
    ((__nv_bfloat162*)g_ulo)[2*i+1] = __nv_bfloat162(__float2bfloat16(v.z - __bfloat162float(hz)),
                                                     __float2bfloat16(v.w - __bfloat162float(hw)));
}

// ================= wx = x @ W^T + Wb via wmma (unchanged, proven) =================
__device__ __forceinline__ void fill_stage(uint32_t sb, int s, int m0, int n0, int k0, int tid) {
    uint32_t sa = sb + s * STAGE_A;
    uint32_t sbb = sb + SMEM_B_OFF + s * STAGE_A;
    #pragma unroll
    for (int j = 0; j < 2; ++j) {
        int idx = tid + j * 256;
        int r = idx >> 2, c = idx & 3;
        cp_async16(sa + r * (LDT * 2) + c * 16, g_xs + (size_t)(m0 + r) * KK + k0 + c * 8);
    }
    #pragma unroll
    for (int j = 0; j < 2; ++j) {
        int idx = tid + j * 256;
        int r = idx >> 2, c = idx & 3;
        cp_async16(sbb + r * (LDT * 2) + c * 16, g_ws + (size_t)(n0 + r) * KK + k0 + c * 8);
    }
    CP_COMMIT();
}

__global__ void __launch_bounds__(256) gemm_wx_mma(float* __restrict__ out,
                                                   const float* __restrict__ Wb) {
    extern __shared__ char smem[];
    uint32_t sb = smem_u32(smem);
    float* biasT = (float*)(smem + SMEM_BIAS_OFF);
    const int tid = threadIdx.x, warp = tid >> 5;
    const int wm = warp & 3, wn = warp >> 2;
    const int n0 = blockIdx.x * BN, m0 = blockIdx.y * BM;

    for (int i = tid; i < 16 * BN; i += 256) biasT[i] = Wb[n0 + (i & (BN - 1))];
    __syncthreads();

    wmma::fragment<wmma::accumulator, 16, 16, 16, float> c[2][4];
    #pragma unroll
    for (int i = 0; i < 2; ++i)
        #pragma unroll
        for (int j = 0; j < 4; ++j)
            wmma::load_matrix_sync(c[i][j], biasT + wn * 64 + j * 16, BN, wmma::mem_row_major);

    fill_stage(sb, 0, m0, n0, 0, tid);
    fill_stage(sb, 1, m0, n0, BK, tid);

    int rs = 0, ws = 2;
    for (int ks = 0; ks < NK; ++ks) {
        asm volatile("cp.async.wait_group 1;" ::: "memory");
        __syncthreads();

        const __nv_bfloat16* As = (const __nv_bfloat16*)(smem + rs * STAGE_A);
        const __nv_bfloat16* Bs = (const __nv_bfloat16*)(smem + SMEM_B_OFF + rs * STAGE_A);
        #pragma unroll
        for (int kk = 0; kk < 2; ++kk) {
            wmma::fragment<wmma::matrix_a, 16, 16, 16, __nv_bfloat16, wmma::row_major> a[2];
            wmma::fragment<wmma::matrix_b, 16, 16, 16, __nv_bfloat16, wmma::col_major> b[4];
            #pragma unroll
            for (int i = 0; i < 2; ++i)
                wmma::load_matrix_sync(a[i], As + (wm * 32 + i * 16) * LDT + kk * 16, LDT);
            #pragma unroll
            for (int j = 0; j < 4; ++j)
                wmma::load_matrix_sync(b[j], Bs + (wn * 64 + j * 16) * LDT + kk * 16, LDT);
            #pragma unroll
            for (int i = 0; i < 2; ++i)
                #pragma unroll
                for (int j = 0; j < 4; ++j)
                    wmma::mma_sync(c[i][j], a[i], b[j], c[i][j]);
        }

        if (ks + 2 < NK) fill_stage(sb, ws, m0, n0, (ks + 2) * BK, tid);
        else CP_COMMIT();
        rs = (rs == 2) ? 0 : rs + 1;
        ws = (ws == 2) ? 0 : ws + 1;
    }

    #pragma unroll
    for (int i = 0; i < 2; ++i)
        #pragma unroll
        for (int j = 0; j < 4; ++j)
            wmma::store_matrix_sync(out + (size_t)(m0 + wm * 32 + i * 16) * D + n0 + wn * 64 + j * 16,
                                    c[i][j], D, wmma::mem_row_major);
}

// ================= persistent HMMA recurrence, (n,b)-partitioned =================
// 128 blocks x 256 threads. Block (ni, bi) owns n-cols [ni*32, +32), batches
// [bi*16, +16). U slice SMEM-resident. Per step: warp self-stages its h slab
// (cp.async), block prefetches wx[t+1] into smem (overlapped), 48 wmma/warp,
// 8-way smem reduction, fused epilogue from smem wx, per-bi 32-block barrier.
__global__ void __launch_bounds__(256, 1) rnn_mma(float* __restrict__ out,
                                                  const float* __restrict__ Ub,
                                                  const float* __restrict__ bias) {
    extern __shared__ char sm[];
    __nv_bfloat16* s_uhi = (__nv_bfloat16*)sm;             // [32][ULD]
    __nv_bfloat16* s_ulo = s_uhi + U_ELEMS;
    __nv_bfloat16* s_hhi = s_ulo + U_ELEMS;                // [16][ULD]
    __nv_bfloat16* s_hlo = s_hhi + H_ELEMS;
    float* s_red = (float*)(s_hlo + H_ELEMS);              // [8 warps][2 nfrag][16][16]
    float* s_wx  = s_red + 8 * 512;                        // [2][16][32]

    const int tid = threadIdx.x, warp = tid >> 5, lane = tid & 31;
    const int ni = blockIdx.x >> 2, bi = blockIdx.x & 3;
    const int n0 = ni * 32, b0 = bi * 16;

    // ---- stage U slice once (full 1024-k rows) ----
    {
        uint32_t duh = smem_u32(s_uhi), dul = smem_u32(s_ulo);
        for (int i = tid; i < 32 * 128; i += 256) {
            int r = i >> 7, c = i & 127;
            cp_async16(duh + (r * ULD + c * 8) * 2, g_uhi + (size_t)(n0 + r) * D + c * 8);
            cp_async16(dul + (r * ULD + c * 8) * 2, g_ulo + (size_t)(n0 + r) * D + c * 8);
        }
        CP_COMMIT();
        asm volatile("cp.async.wait_group 0;" ::: "memory");
        __syncthreads();
    }

    const int kc0 = warp * 128;
    const uint32_t shh = smem_u32(s_hhi), shl = smem_u32(s_hlo);
    const uint32_t swx = smem_u32(s_wx);

    // ---- wx prefetch geometry: threads 0..127 move one 16B chunk each ----
    const int pr = tid >> 3, pc = tid & 7;                 // row 0..15, chunk 0..7
    const float* wx_src0 = out + (size_t)(b0 + pr) * (T * D) + n0 + pc * 4;
    const uint32_t wx_doff = (pr * 32 + pc * 4) * 4;

    // ---- epilogue constants ----
    const int eb  = tid >> 4;
    const int enl = (tid & 15) * 2;
    float2 cconst;
    cconst.x = Ub[n0 + enl]     + bias[n0 + enl];
    cconst.y = Ub[n0 + enl + 1] + bias[n0 + enl + 1];
    const size_t obase = (size_t)(b0 + eb) * (T * D) + n0 + enl;
    const int    hbase = (b0 + eb) * D + n0 + enl;
    const int    efr   = enl >> 4;
    const int    ec    = enl & 15;

    volatile unsigned* ctr = &g_ctrs[bi];

    // ---- prologue: prefetch wx[0] ----
    if (tid < 128) cp_async16(swx + wx_doff, wx_src0);
    CP_COMMIT();

    for (int t = 0; t < T; ++t) {
        const __nv_bfloat16* Hhi = g_hhi[t & 1];
        const __nv_bfloat16* Hlo = g_hlo[t & 1];

        // ---- self-stage this warp's h slab: 16 rows x 128 k, hi+lo ----
        #pragma unroll
        for (int j = 0; j < 8; ++j) {
            int i = lane + j * 32;
            int r = i >> 4, c = i & 15;
            uint32_t off = (r * ULD + kc0 + c * 8) * 2;
            const size_t goff = (size_t)(b0 + r) * D + kc0 + c * 8;
            cp_async16(shh + off, Hhi + goff);
            cp_async16(shl + off, Hlo + goff);
        }
        CP_COMMIT();

        // ---- prefetch wx[t+1] into the other smem buffer (overlaps compute) ----
        if (t + 1 < T && tid < 128)
            cp_async16(swx + ((t + 1) & 1) * 2048 + wx_doff, wx_src0 + (size_t)(t + 1) * D);
        CP_COMMIT();

        // completes h[t] and wx[t]; wx[t+1] may still fly
        asm volatile("cp.async.wait_group 1;" ::: "memory");
        __syncwarp();

        // ---- compute: M=16(b) x N=32 x K=128, 3 products ----
        wmma::fragment<wmma::accumulator, 16, 16, 16, float> acc[2];
        wmma::fill_fragment(acc[0], 0.f);
        wmma::fill_fragment(acc[1], 0.f);
        #pragma unroll
        for (int ks = 0; ks < 8; ++ks) {
            const int kg = kc0 + ks * 16;
            wmma::fragment<wmma::matrix_a, 16, 16, 16, __nv_bfloat16, wmma::row_major> ah, al;
            wmma::load_matrix_sync(ah, s_hhi + kg, ULD);
            wmma::load_matrix_sync(al, s_hlo + kg, ULD);
            #pragma unroll
            for (int j = 0; j < 2; ++j) {
                wmma::fragment<wmma::matrix_b, 16, 16, 16, __nv_bfloat16, wmma::col_major> bh, bl;
                wmma::load_matrix_sync(bh, s_uhi + (size_t)(j * 16) * ULD + kg, ULD);
                wmma::load_matrix_sync(bl, s_ulo + (size_t)(j * 16) * ULD + kg, ULD);
                wmma::mma_sync(acc[j], ah, bh, acc[j]);
                wmma::mma_sync(acc[j], al, bh, acc[j]);
                wmma::mma_sync(acc[j], ah, bl, acc[j]);
            }
        }
        wmma::store_matrix_sync(s_red + warp * 512,       acc[0], 16, wmma::mem_row_major);
        wmma::store_matrix_sync(s_red + warp * 512 + 256, acc[1], 16, wmma::mem_row_major);
        __syncthreads();

        // ---- 8-way K reduction + fused epilogue (wx from smem) ----
        {
            const float* p = s_red + efr * 256 + eb * 16 + ec;
            float s0 = 0.f, s1 = 0.f;
            #pragma unroll
            for (int w = 0; w < 8; ++w) { s0 += p[w * 512]; s1 += p[w * 512 + 1]; }
            const float* wxp = s_wx + (t & 1) * 512 + eb * 32 + enl;
            float zx = tanhf(wxp[0] + s0 + cconst.x);
            float zy = tanhf(wxp[1] + s1 + cconst.y);
            *(float2*)(out + obase + (size_t)t * D) = make_float2(zx, zy);

            __nv_bfloat16 hx = __float2bfloat16(zx), hy = __float2bfloat16(zy);
            *(__nv_bfloat162*)(g_hhi[(t + 1) & 1] + hbase) = __nv_bfloat162(hx, hy);
            *(__nv_bfloat162*)(g_hlo[(t + 1) & 1] + hbase) =
                __nv_bfloat162(__float2bfloat16(zx - __bfloat162float(hx)),
                               __float2bfloat16(zy - __bfloat162float(hy)));
        }

        // ---- per-bi grid barrier (32 blocks) ----
        __threadfence();
        __syncthreads();
        if (tid == 0) {
            atomicAdd((unsigned*)ctr, 1u);
            unsigned target = (unsigned)(t + 1) * 32;
            while (*ctr < target) { }
            __threadfence();
        }
        __syncthreads();
    }
}

// ---------------- copy final hidden state into hx region ----------------
__global__ void copy_hx(float* __restrict__ out) {
    int i = blockIdx.x * blockDim.x + threadIdx.x;
    if (i < B * D) {
        int b = i >> 10, n = i & (D - 1);
        out[(size_t)B * T * D + i] = out[(size_t)b * T * D + (size_t)(T - 1) * D + n];
    }
}

extern "C" void kernel_launch(void* const* d_in, const int* in_sizes, int n_in,
                              void* d_out, int out_size) {
    const float* x    = (const float*)d_in[0];
    const float* Ww   = (const float*)d_in[1];
    const float* Wb   = (const float*)d_in[2];
    const float* Uw   = (const float*)d_in[3];
    const float* Ub   = (const float*)d_in[4];
    const float* bias = (const float*)d_in[5];
    float* out = (float*)d_out;

    cudaFuncSetAttribute(gemm_wx_mma, cudaFuncAttributeMaxDynamicSharedMemorySize, GEMM_SMEM);
    cudaFuncSetAttribute(rnn_mma,     cudaFuncAttributeMaxDynamicSharedMemorySize, RNN_SMEM);

    zero_h0<<<(B * D + 255) / 256, 256>>>();
    split_x<<<((size_t)B * T * D / 4) / 256, 256>>>(x);
    split_w<<<(D * D / 4) / 256, 256>>>(Ww);
    split_U<<<(D * D / 4) / 256, 256>>>(Uw);
    gemm_wx_mma<<<dim3(D / BN, (B * T) / BM), 256, GEMM_SMEM>>>(out, Wb);
    rnn_mma<<<RBLK, 256, RNN_SMEM>>>(out, Ub, bias);
    copy_hx<<<(B * D + 255) / 256, 256>>>(out);
}

// round 9
// speedup vs baseline: 1.7885x; 1.0572x over previous
#include <cuda_runtime.h>
#include <cuda_bf16.h>
#include <mma.h>
#include <math.h>
#include <stdint.h>

using namespace nvcuda;

#define B 64
#define T 512
#define D 1024
#define RBLK 128          // recurrence grid: 32 n-splits x 4 b-splits

// ---------------- wx GEMM config (K-concat hi/lo trick, K'=3072) ----------------
#define KK 3072
#define BM 128
#define BN 128
#define BK 32
#define NK (KK / BK)
#define LDT 40
#define STAGE_A (BM * LDT * 2)
#define AB_STAGES 3
#define SMEM_B_OFF (AB_STAGES * STAGE_A)
#define SMEM_BIAS_OFF (2 * AB_STAGES * STAGE_A)
#define GEMM_SMEM (SMEM_BIAS_OFF + 16 * BN * 4)

// ---------------- recurrence smem config ----------------
#define ULD 1032                               // padded k-stride (bf16 elems)
#define U_ELEMS (32 * ULD)                     // 32 n-rows x 1032
#define H_ELEMS (16 * ULD)                     // 16 b-rows x 1032
// layout: s_uhi | s_ulo | s_hhi | s_hlo | s_red | s_wx(2x512 fp32)
#define RNN_SMEM ((2 * U_ELEMS + 2 * H_ELEMS) * 2 + 8 * 512 * 4 + 2 * 512 * 4)  // 218624 B

// ---------------- scratch ----------------
__device__ unsigned g_flags[4][32][32];                // per-(bi,ni) step flags, 128B padded
__device__ __nv_bfloat16 g_xs[(size_t)B * T * KK];     // x split K-concat [hi|lo|hi]
__device__ __nv_bfloat16 g_ws[(size_t)D * KK];         // W split K-concat [hi|hi|lo]
__device__ __nv_bfloat16 g_hhi[2][B * D];              // h hi, double buffered
__device__ __nv_bfloat16 g_hlo[2][B * D];              // h lo
__device__ __nv_bfloat16 g_uhi[D * D];                 // U hi, row-major [n][k]
__device__ __nv_bfloat16 g_ulo[D * D];                 // U lo

// ---------------- helpers ----------------
__device__ __forceinline__ uint32_t smem_u32(const void* p) {
    uint32_t a;
    asm("{ .reg .u64 t; cvta.to.shared.u64 t, %1; cvt.u32.u64 %0, t; }" : "=r"(a) : "l"(p));
    return a;
}
__device__ __forceinline__ void cp_async16(uint32_t dst, const void* src) {
    asm volatile("cp.async.cg.shared.global [%0], [%1], 16;" :: "r"(dst), "l"(src) : "memory");
}
#define CP_COMMIT() asm volatile("cp.async.commit_group;" ::: "memory")

// ---------------- init: zero h0 and the exchange flags ----------------
__global__ void zero_h0() {
    int i = blockIdx.x * blockDim.x + threadIdx.x;
    if (i < B * D) {
        g_hhi[0][i] = __nv_bfloat16(0.f);
        g_hlo[0][i] = __nv_bfloat16(0.f);
    }
    if (i < 128) g_flags[i >> 5][i & 31][0] = 0;
}

// ---------------- fp32 -> bf16 splits ----------------
__global__ void split_x(const float* __restrict__ s) {
    size_t i = (size_t)blockIdx.x * blockDim.x + threadIdx.x;
    float4 v = ((const float4*)s)[i];
    size_t e = i * 4;
    size_t m = e >> 10;
    int    k = (int)(e & 1023);
    __nv_bfloat16 hx = __float2bfloat16(v.x), hy = __float2bfloat16(v.y);
    __nv_bfloat16 hz = __float2bfloat16(v.z), hw = __float2bfloat16(v.w);
    __nv_bfloat162 h01(hx, hy), h23(hz, hw);
    __nv_bfloat162 l01(__float2bfloat16(v.x - __bfloat162float(hx)),
                       __float2bfloat16(v.y - __bfloat162float(hy)));
    __nv_bfloat162 l23(__float2bfloat16(v.z - __bfloat162float(hz)),
                       __float2bfloat16(v.w - __bfloat162float(hw)));
    __nv_bfloat16* row = g_xs + m * KK;
    *(__nv_bfloat162*)(row + k)       = h01;  *(__nv_bfloat162*)(row + k + 2)       = h23;
    *(__nv_bfloat162*)(row + D + k)   = l01;  *(__nv_bfloat162*)(row + D + k + 2)   = l23;
    *(__nv_bfloat162*)(row + 2*D + k) = h01;  *(__nv_bfloat162*)(row + 2*D + k + 2) = h23;
}
__global__ void split_w(const float* __restrict__ s) {
    size_t i = (size_t)blockIdx.x * blockDim.x + threadIdx.x;
    float4 v = ((const float4*)s)[i];
    size_t e = i * 4;
    size_t n = e >> 10;
    int    k = (int)(e & 1023);
    __nv_bfloat16 hx = __float2bfloat16(v.x), hy = __float2bfloat16(v.y);
    __nv_bfloat16 hz = __float2bfloat16(v.z), hw = __float2bfloat16(v.w);
    __nv_bfloat162 h01(hx, hy), h23(hz, hw);
    __nv_bfloat162 l01(__float2bfloat16(v.x - __bfloat162float(hx)),
                       __float2bfloat16(v.y - __bfloat162float(hy)));
    __nv_bfloat162 l23(__float2bfloat16(v.z - __bfloat162float(hz)),
                       __float2bfloat16(v.w - __bfloat162float(hw)));
    __nv_bfloat16* row = g_ws + n * KK;
    *(__nv_bfloat162*)(row + k)       = h01;  *(__nv_bfloat162*)(row + k + 2)       = h23;
    *(__nv_bfloat162*)(row + D + k)   = h01;  *(__nv_bfloat162*)(row + D + k + 2)   = h23;
    *(__nv_bfloat162*)(row + 2*D + k) = l01;  *(__nv_bfloat162*)(row + 2*D + k + 2) = l23;
}
__global__ void split_U(const float* __restrict__ s) {
    size_t i = (size_t)blockIdx.x * blockDim.x + threadIdx.x;
    float4 v = ((const float4*)s)[i];
    __nv_bfloat16 hx = __float2bfloat16(v.x), hy = __float2bfloat16(v.y);
    __nv_bfloat16 hz = __float2bfloat16(v.z), hw = __float2bfloat16(v.w);
    ((__nv_bfloat162*)g_uhi)[2*i]   = __nv_bfloat162(hx, hy);
    ((__nv_bfloat162*)g_uhi)[2*i+1] = __nv_bfloat162(hz, hw);
    ((__nv_bfloat162*)g_ulo)[2*i]   = __nv_bfloat162(__float2bfloat16(v.x - __bfloat162float(hx)),
                                                     __float2bfloat16(v.y - __bfloat162float(hy)));
    ((__nv_bfloat162*)g_ulo)[2*i+1] = __nv_bfloat162(__float2bfloat16(v.z - __bfloat162float(hz)),
                                                     __float2bfloat16(v.w - __bfloat162float(hw)));
}

// ================= wx = x @ W^T + Wb via wmma (unchanged, proven) =================
__device__ __forceinline__ void fill_stage(uint32_t sb, int s, int m0, int n0, int k0, int tid) {
    uint32_t sa = sb + s * STAGE_A;
    uint32_t sbb = sb + SMEM_B_OFF + s * STAGE_A;
    #pragma unroll
    for (int j = 0; j < 2; ++j) {
        int idx = tid + j * 256;
        int r = idx >> 2, c = idx & 3;
        cp_async16(sa + r * (LDT * 2) + c * 16, g_xs + (size_t)(m0 + r) * KK + k0 + c * 8);
    }
    #pragma unroll
    for (int j = 0; j < 2; ++j) {
        int idx = tid + j * 256;
        int r = idx >> 2, c = idx & 3;
        cp_async16(sbb + r * (LDT * 2) + c * 16, g_ws + (size_t)(n0 + r) * KK + k0 + c * 8);
    }
    CP_COMMIT();
}

__global__ void __launch_bounds__(256) gemm_wx_mma(float* __restrict__ out,
                                                   const float* __restrict__ Wb) {
    extern __shared__ char smem[];
    uint32_t sb = smem_u32(smem);
    float* biasT = (float*)(smem + SMEM_BIAS_OFF);
    const int tid = threadIdx.x, warp = tid >> 5;
    const int wm = warp & 3, wn = warp >> 2;
    const int n0 = blockIdx.x * BN, m0 = blockIdx.y * BM;

    for (int i = tid; i < 16 * BN; i += 256) biasT[i] = Wb[n0 + (i & (BN - 1))];
    __syncthreads();

    wmma::fragment<wmma::accumulator, 16, 16, 16, float> c[2][4];
    #pragma unroll
    for (int i = 0; i < 2; ++i)
        #pragma unroll
        for (int j = 0; j < 4; ++j)
            wmma::load_matrix_sync(c[i][j], biasT + wn * 64 + j * 16, BN, wmma::mem_row_major);

    fill_stage(sb, 0, m0, n0, 0, tid);
    fill_stage(sb, 1, m0, n0, BK, tid);

    int rs = 0, ws = 2;
    for (int ks = 0; ks < NK; ++ks) {
        asm volatile("cp.async.wait_group 1;" ::: "memory");
        __syncthreads();

        const __nv_bfloat16* As = (const __nv_bfloat16*)(smem + rs * STAGE_A);
        const __nv_bfloat16* Bs = (const __nv_bfloat16*)(smem + SMEM_B_OFF + rs * STAGE_A);
        #pragma unroll
        for (int kk = 0; kk < 2; ++kk) {
            wmma::fragment<wmma::matrix_a, 16, 16, 16, __nv_bfloat16, wmma::row_major> a[2];
            wmma::fragment<wmma::matrix_b, 16, 16, 16, __nv_bfloat16, wmma::col_major> b[4];
            #pragma unroll
            for (int i = 0; i < 2; ++i)
                wmma::load_matrix_sync(a[i], As + (wm * 32 + i * 16) * LDT + kk * 16, LDT);
            #pragma unroll
            for (int j = 0; j < 4; ++j)
                wmma::load_matrix_sync(b[j], Bs + (wn * 64 + j * 16) * LDT + kk * 16, LDT);
            #pragma unroll
            for (int i = 0; i < 2; ++i)
                #pragma unroll
                for (int j = 0; j < 4; ++j)
                    wmma::mma_sync(c[i][j], a[i], b[j], c[i][j]);
        }

        if (ks + 2 < NK) fill_stage(sb, ws, m0, n0, (ks + 2) * BK, tid);
        else CP_COMMIT();
        rs = (rs == 2) ? 0 : rs + 1;
        ws = (ws == 2) ? 0 : ws + 1;
    }

    #pragma unroll
    for (int i = 0; i < 2; ++i)
        #pragma unroll
        for (int j = 0; j < 4; ++j)
            wmma::store_matrix_sync(out + (size_t)(m0 + wm * 32 + i * 16) * D + n0 + wn * 64 + j * 16,
                                    c[i][j], D, wmma::mem_row_major);
}

// ================= persistent HMMA recurrence, flag-synced =================
// 128 blocks x 256 threads. Block (ni, bi) owns n-cols [ni*32, +32), batches
// [bi*16, +16). U slice SMEM-resident. Producer/consumer step flags replace
// the group barrier: warp w only waits on the 4 producers covering its
// k-chunk, then stages h immediately. Epilogue publishes flag[bi][ni] = t+1.
__global__ void __launch_bounds__(256, 1) rnn_mma(float* __restrict__ out,
                                                  const float* __restrict__ Ub,
                                                  const float* __restrict__ bias) {
    extern __shared__ char sm[];
    __nv_bfloat16* s_uhi = (__nv_bfloat16*)sm;             // [32][ULD]
    __nv_bfloat16* s_ulo = s_uhi + U_ELEMS;
    __nv_bfloat16* s_hhi = s_ulo + U_ELEMS;                // [16][ULD]
    __nv_bfloat16* s_hlo = s_hhi + H_ELEMS;
    float* s_red = (float*)(s_hlo + H_ELEMS);              // [8 warps][2 nfrag][16][16]
    float* s_wx  = s_red + 8 * 512;                        // [2][16][32]

    const int tid = threadIdx.x, warp = tid >> 5, lane = tid & 31;
    const int ni = blockIdx.x >> 2, bi = blockIdx.x & 3;
    const int n0 = ni * 32, b0 = bi * 16;

    // ---- stage U slice once (full 1024-k rows) ----
    {
        uint32_t duh = smem_u32(s_uhi), dul = smem_u32(s_ulo);
        for (int i = tid; i < 32 * 128; i += 256) {
            int r = i >> 7, c = i & 127;
            cp_async16(duh + (r * ULD + c * 8) * 2, g_uhi + (size_t)(n0 + r) * D + c * 8);
            cp_async16(dul + (r * ULD + c * 8) * 2, g_ulo + (size_t)(n0 + r) * D + c * 8);
        }
        CP_COMMIT();
        asm volatile("cp.async.wait_group 0;" ::: "memory");
        __syncthreads();
    }

    const int kc0 = warp * 128;
    const uint32_t shh = smem_u32(s_hhi), shl = smem_u32(s_hlo);
    const uint32_t swx = smem_u32(s_wx);

    // this warp's 4 producer flags (one per lane 0-3)
    volatile unsigned* myflag = (lane < 4) ? &g_flags[bi][(warp << 2) + lane][0] : 0;

    // ---- wx prefetch geometry: threads 0..127 move one 16B chunk each ----
    const int pr = tid >> 3, pc = tid & 7;
    const float* wx_src0 = out + (size_t)(b0 + pr) * (T * D) + n0 + pc * 4;
    const uint32_t wx_doff = (pr * 32 + pc * 4) * 4;

    // ---- epilogue constants ----
    const int eb  = tid >> 4;
    const int enl = (tid & 15) * 2;
    float2 cconst;
    cconst.x = Ub[n0 + enl]     + bias[n0 + enl];
    cconst.y = Ub[n0 + enl + 1] + bias[n0 + enl + 1];
    const size_t obase = (size_t)(b0 + eb) * (T * D) + n0 + enl;
    const int    hbase = (b0 + eb) * D + n0 + enl;
    const int    efr   = enl >> 4;
    const int    ec    = enl & 15;

    // ---- prologue: prefetch wx[0] ----
    if (tid < 128) cp_async16(swx + wx_doff, wx_src0);
    CP_COMMIT();

    for (int t = 0; t < T; ++t) {
        const __nv_bfloat16* Hhi = g_hhi[t & 1];
        const __nv_bfloat16* Hlo = g_hlo[t & 1];

        // ---- wait only for this warp's 4 producers (no-op at t=0) ----
        if (lane < 4) { while (*myflag < (unsigned)t) { } }
        __syncwarp();

        // ---- self-stage this warp's h slab: 16 rows x 128 k, hi+lo ----
        #pragma unroll
        for (int j = 0; j < 8; ++j) {
            int i = lane + j * 32;
            int r = i >> 4, c = i & 15;
            uint32_t off = (r * ULD + kc0 + c * 8) * 2;
            const size_t goff = (size_t)(b0 + r) * D + kc0 + c * 8;
            cp_async16(shh + off, Hhi + goff);
            cp_async16(shl + off, Hlo + goff);
        }
        CP_COMMIT();

        // ---- prefetch wx[t+1] into the other smem buffer (overlaps compute) ----
        if (t + 1 < T && tid < 128)
            cp_async16(swx + ((t + 1) & 1) * 2048 + wx_doff, wx_src0 + (size_t)(t + 1) * D);
        CP_COMMIT();

        // completes h[t] and wx[t]; wx[t+1] may still fly
        asm volatile("cp.async.wait_group 1;" ::: "memory");
        __syncwarp();

        // ---- compute: M=16(b) x N=32 x K=128, 3 products ----
        wmma::fragment<wmma::accumulator, 16, 16, 16, float> acc[2];
        wmma::fill_fragment(acc[0], 0.f);
        wmma::fill_fragment(acc[1], 0.f);
        #pragma unroll
        for (int ks = 0; ks < 8; ++ks) {
            const int kg = kc0 + ks * 16;
            wmma::fragment<wmma::matrix_a, 16, 16, 16, __nv_bfloat16, wmma::row_major> ah, al;
            wmma::load_matrix_sync(ah, s_hhi + kg, ULD);
            wmma::load_matrix_sync(al, s_hlo + kg, ULD);
            #pragma unroll
            for (int j = 0; j < 2; ++j) {
                wmma::fragment<wmma::matrix_b, 16, 16, 16, __nv_bfloat16, wmma::col_major> bh, bl;
                wmma::load_matrix_sync(bh, s_uhi + (size_t)(j * 16) * ULD + kg, ULD);
                wmma::load_matrix_sync(bl, s_ulo + (size_t)(j * 16) * ULD + kg, ULD);
                wmma::mma_sync(acc[j], ah, bh, acc[j]);
                wmma::mma_sync(acc[j], al, bh, acc[j]);
                wmma::mma_sync(acc[j], ah, bl, acc[j]);
            }
        }
        wmma::store_matrix_sync(s_red + warp * 512,       acc[0], 16, wmma::mem_row_major);
        wmma::store_matrix_sync(s_red + warp * 512 + 256, acc[1], 16, wmma::mem_row_major);
        __syncthreads();

        // ---- 8-way K reduction + fused epilogue (wx from smem) ----
        {
            const float* p = s_red + efr * 256 + eb * 16 + ec;
            float s0 = 0.f, s1 = 0.f;
            #pragma unroll
            for (int w = 0; w < 8; ++w) { s0 += p[w * 512]; s1 += p[w * 512 + 1]; }
            const float* wxp = s_wx + (t & 1) * 512 + eb * 32 + enl;
            float zx = tanhf(wxp[0] + s0 + cconst.x);
            float zy = tanhf(wxp[1] + s1 + cconst.y);
            *(float2*)(out + obase + (size_t)t * D) = make_float2(zx, zy);
            if (t == T - 1)   // fused copy_hx: hx[b, n] = h_T
                *(float2*)(out + (size_t)B * T * D + hbase) = make_float2(zx, zy);

            __nv_bfloat16 hx = __float2bfloat16(zx), hy = __float2bfloat16(zy);
            *(__nv_bfloat162*)(g_hhi[(t + 1) & 1] + hbase) = __nv_bfloat162(hx, hy);
            *(__nv_bfloat162*)(g_hlo[(t + 1) & 1] + hbase) =
                __nv_bfloat162(__float2bfloat16(zx - __bfloat162float(hx)),
                               __float2bfloat16(zy - __bfloat162float(hy)));
        }

        // ---- publish: h[t+1] rows for this (bi, ni) are ready ----
        __syncthreads();
        if (tid == 0) {
            __threadfence();
            *(volatile unsigned*)&g_flags[bi][ni][0] = (unsigned)(t + 1);
        }
    }
}

extern "C" void kernel_launch(void* const* d_in, const int* in_sizes, int n_in,
                              void* d_out, int out_size) {
    const float* x    = (const float*)d_in[0];
    const float* Ww   = (const float*)d_in[1];
    const float* Wb   = (const float*)d_in[2];
    const float* Uw   = (const float*)d_in[3];
    const float* Ub   = (const float*)d_in[4];
    const float* bias = (const float*)d_in[5];
    float* out = (float*)d_out;

    cudaFuncSetAttribute(gemm_wx_mma, cudaFuncAttributeMaxDynamicSharedMemorySize, GEMM_SMEM);
    cudaFuncSetAttribute(rnn_mma,     cudaFuncAttributeMaxDynamicSharedMemorySize, RNN_SMEM);

    zero_h0<<<(B * D + 255) / 256, 256>>>();
    split_x<<<((size_t)B * T * D / 4) / 256, 256>>>(x);
    split_w<<<(D * D / 4) / 256, 256>>>(Ww);
    split_U<<<(D * D / 4) / 256, 256>>>(Uw);
    gemm_wx_mma<<<dim3(D / BN, (B * T) / BM), 256, GEMM_SMEM>>>(out, Wb);
    rnn_mma<<<RBLK, 256, RNN_SMEM>>>(out, Ub, bias);
}

// round 10
// speedup vs baseline: 2.0500x; 1.1462x over previous
#include <cuda_runtime.h>
#include <cuda_bf16.h>
#include <mma.h>
#include <math.h>
#include <stdint.h>

using namespace nvcuda;

#define B 64
#define T 512
#define D 1024
#define RBLK 128          // recurrence grid: 32 n-splits x 4 b-splits

// ---------------- wx GEMM config (K-concat hi/lo trick, K'=3072) ----------------
#define KK 3072
#define BM 128
#define BN 128
#define BK 32
#define NK (KK / BK)
#define LDT 40
#define STAGE_A (BM * LDT * 2)
#define AB_STAGES 3
#define SMEM_B_OFF (AB_STAGES * STAGE_A)
#define SMEM_BIAS_OFF (2 * AB_STAGES * STAGE_A)
#define GEMM_SMEM (SMEM_BIAS_OFF + 16 * BN * 4)

// ---------------- recurrence smem config ----------------
#define ULD 1032                               // padded k-stride (bf16 elems)
#define U_ELEMS (32 * ULD)                     // 32 n-rows x 1032
#define H_ELEMS (16 * ULD)                     // 16 b-rows x 1032
// layout: s_uhi | s_ulo | s_hhi | s_hlo | s_red | s_wx(2x512 fp32)
#define RNN_SMEM ((2 * U_ELEMS + 2 * H_ELEMS) * 2 + 8 * 512 * 4 + 2 * 512 * 4)  // 218624 B

// ---------------- scratch ----------------
__device__ unsigned g_flags[4][32][8][8];              // per-(bi,ni,warp) step flags, 32B padded
__device__ __nv_bfloat16 g_xs[(size_t)B * T * KK];     // x split K-concat [hi|lo|hi]
__device__ __nv_bfloat16 g_ws[(size_t)D * KK];         // W split K-concat [hi|hi|lo]
__device__ __nv_bfloat16 g_hhi[2][B * D];              // h hi, double buffered
__device__ __nv_bfloat16 g_hlo[2][B * D];              // h lo
__device__ __nv_bfloat16 g_uhi[D * D];                 // U hi, row-major [n][k]
__device__ __nv_bfloat16 g_ulo[D * D];                 // U lo

// ---------------- helpers ----------------
__device__ __forceinline__ uint32_t smem_u32(const void* p) {
    uint32_t a;
    asm("{ .reg .u64 t; cvta.to.shared.u64 t, %1; cvt.u32.u64 %0, t; }" : "=r"(a) : "l"(p));
    return a;
}
__device__ __forceinline__ void cp_async16(uint32_t dst, const void* src) {
    asm volatile("cp.async.cg.shared.global [%0], [%1], 16;" :: "r"(dst), "l"(src) : "memory");
}
#define CP_COMMIT() asm volatile("cp.async.commit_group;" ::: "memory")

// ---------------- init: zero h0 and the exchange flags ----------------
__global__ void zero_h0() {
    int i = blockIdx.x * blockDim.x + threadIdx.x;
    if (i < B * D) {
        g_hhi[0][i] = __nv_bfloat16(0.f);
        g_hlo[0][i] = __nv_bfloat16(0.f);
    }
    if (i < 4 * 32 * 8) g_flags[i >> 8][(i >> 3) & 31][i & 7][0] = 0;
}

// ---------------- fp32 -> bf16 splits ----------------
__global__ void split_x(const float* __restrict__ s) {
    size_t i = (size_t)blockIdx.x * blockDim.x + threadIdx.x;
    float4 v = ((const float4*)s)[i];
    size_t e = i * 4;
    size_t m = e >> 10;
    int    k = (int)(e & 1023);
    __nv_bfloat16 hx = __float2bfloat16(v.x), hy = __float2bfloat16(v.y);
    __nv_bfloat16 hz = __float2bfloat16(v.z), hw = __float2bfloat16(v.w);
    __nv_bfloat162 h01(hx, hy), h23(hz, hw);
    __nv_bfloat162 l01(__float2bfloat16(v.x - __bfloat162float(hx)),
                       __float2bfloat16(v.y - __bfloat162float(hy)));
    __nv_bfloat162 l23(__float2bfloat16(v.z - __bfloat162float(hz)),
                       __float2bfloat16(v.w - __bfloat162float(hw)));
    __nv_bfloat16* row = g_xs + m * KK;
    *(__nv_bfloat162*)(row + k)       = h01;  *(__nv_bfloat162*)(row + k + 2)       = h23;
    *(__nv_bfloat162*)(row + D + k)   = l01;  *(__nv_bfloat162*)(row + D + k + 2)   = l23;
    *(__nv_bfloat162*)(row + 2*D + k) = h01;  *(__nv_bfloat162*)(row + 2*D + k + 2) = h23;
}
__global__ void split_w(const float* __restrict__ s) {
    size_t i = (size_t)blockIdx.x * blockDim.x + threadIdx.x;
    float4 v = ((const float4*)s)[i];
    size_t e = i * 4;
    size_t n = e >> 10;
    int    k = (int)(e & 1023);
    __nv_bfloat16 hx = __float2bfloat16(v.x), hy = __float2bfloat16(v.y);
    __nv_bfloat16 hz = __float2bfloat16(v.z), hw = __float2bfloat16(v.w);
    __nv_bfloat162 h01(hx, hy), h23(hz, hw);
    __nv_bfloat162 l01(__float2bfloat16(v.x - __bfloat162float(hx)),
                       __float2bfloat16(v.y - __bfloat162float(hy)));
    __nv_bfloat162 l23(__float2bfloat16(v.z - __bfloat162float(hz)),
                       __float2bfloat16(v.w - __bfloat162float(hw)));
    __nv_bfloat16* row = g_ws + n * KK;
    *(__nv_bfloat162*)(row + k)       = h01;  *(__nv_bfloat162*)(row + k + 2)       = h23;
    *(__nv_bfloat162*)(row + D + k)   = h01;  *(__nv_bfloat162*)(row + D + k + 2)   = h23;
    *(__nv_bfloat162*)(row + 2*D + k) = l01;  *(__nv_bfloat162*)(row + 2*D + k + 2) = l23;
}
__global__ void split_U(const float* __restrict__ s) {
    size_t i = (size_t)blockIdx.x * blockDim.x + threadIdx.x;
    float4 v = ((const float4*)s)[i];
    __nv_bfloat16 hx = __float2bfloat16(v.x), hy = __float2bfloat16(v.y);
    __nv_bfloat16 hz = __float2bfloat16(v.z), hw = __float2bfloat16(v.w);
    ((__nv_bfloat162*)g_uhi)[2*i]   = __nv_bfloat162(hx, hy);
    ((__nv_bfloat162*)g_uhi)[2*i+1] = __nv_bfloat162(hz, hw);
    ((__nv_bfloat162*)g_ulo)[2*i]   = __nv_bfloat162(__float2bfloat16(v.x - __bfloat162float(hx)),
                                                     __float2bfloat16(v.y - __bfloat162float(hy)));
    ((__nv_bfloat162*)g_ulo)[2*i+1] = __nv_bfloat162(__float2bfloat16(v.z - __bfloat162float(hz)),
                                                     __float2bfloat16(v.w - __bfloat162float(hw)));
}

// ================= wx = x @ W^T + Wb via wmma (unchanged, proven) =================
__device__ __forceinline__ void fill_stage(uint32_t sb, int s, int m0, int n0, int k0, int tid) {
    uint32_t sa = sb + s * STAGE_A;
    uint32_t sbb = sb + SMEM_B_OFF + s * STAGE_A;
    #pragma unroll
    for (int j = 0; j < 2; ++j) {
        int idx = tid + j * 256;
        int r = idx >> 2, c = idx & 3;
        cp_async16(sa + r * (LDT * 2) + c * 16, g_xs + (size_t)(m0 + r) * KK + k0 + c * 8);
    }
    #pragma unroll
    for (int j = 0; j < 2; ++j) {
        int idx = tid + j * 256;
        int r = idx >> 2, c = idx & 3;
        cp_async16(sbb + r * (LDT * 2) + c * 16, g_ws + (size_t)(n0 + r) * KK + k0 + c * 8);
    }
    CP_COMMIT();
}

__global__ void __launch_bounds__(256) gemm_wx_mma(float* __restrict__ out,
                                                   const float* __restrict__ Wb) {
    extern __shared__ char smem[];
    uint32_t sb = smem_u32(smem);
    float* biasT = (float*)(smem + SMEM_BIAS_OFF);
    const int tid = threadIdx.x, warp = tid >> 5;
    const int wm = warp & 3, wn = warp >> 2;
    const int n0 = blockIdx.x * BN, m0 = blockIdx.y * BM;

    for (int i = tid; i < 16 * BN; i += 256) biasT[i] = Wb[n0 + (i & (BN - 1))];
    __syncthreads();

    wmma::fragment<wmma::accumulator, 16, 16, 16, float> c[2][4];
    #pragma unroll
    for (int i = 0; i < 2; ++i)
        #pragma unroll
        for (int j = 0; j < 4; ++j)
            wmma::load_matrix_sync(c[i][j], biasT + wn * 64 + j * 16, BN, wmma::mem_row_major);

    fill_stage(sb, 0, m0, n0, 0, tid);
    fill_stage(sb, 1, m0, n0, BK, tid);

    int rs = 0, ws = 2;
    for (int ks = 0; ks < NK; ++ks) {
        asm volatile("cp.async.wait_group 1;" ::: "memory");
        __syncthreads();

        const __nv_bfloat16* As = (const __nv_bfloat16*)(smem + rs * STAGE_A);
        const __nv_bfloat16* Bs = (const __nv_bfloat16*)(smem + SMEM_B_OFF + rs * STAGE_A);
        #pragma unroll
        for (int kk = 0; kk < 2; ++kk) {
            wmma::fragment<wmma::matrix_a, 16, 16, 16, __nv_bfloat16, wmma::row_major> a[2];
            wmma::fragment<wmma::matrix_b, 16, 16, 16, __nv_bfloat16, wmma::col_major> b[4];
            #pragma unroll
            for (int i = 0; i < 2; ++i)
                wmma::load_matrix_sync(a[i], As + (wm * 32 + i * 16) * LDT + kk * 16, LDT);
            #pragma unroll
            for (int j = 0; j < 4; ++j)
                wmma::load_matrix_sync(b[j], Bs + (wn * 64 + j * 16) * LDT + kk * 16, LDT);
            #pragma unroll
            for (int i = 0; i < 2; ++i)
                #pragma unroll
                for (int j = 0; j < 4; ++j)
                    wmma::mma_sync(c[i][j], a[i], b[j], c[i][j]);
        }

        if (ks + 2 < NK) fill_stage(sb, ws, m0, n0, (ks + 2) * BK, tid);
        else CP_COMMIT();
        rs = (rs == 2) ? 0 : rs + 1;
        ws = (ws == 2) ? 0 : ws + 1;
    }

    #pragma unroll
    for (int i = 0; i < 2; ++i)
        #pragma unroll
        for (int j = 0; j < 4; ++j)
            wmma::store_matrix_sync(out + (size_t)(m0 + wm * 32 + i * 16) * D + n0 + wn * 64 + j * 16,
                                    c[i][j], D, wmma::mem_row_major);
}

// ================= persistent HMMA recurrence, flag-synced, reg-pinned U =================
// 128 blocks x 256 threads. Block (ni, bi) owns n-cols [ni*32, +32), batches
// [bi*16, +16). U fragments (hi+lo, 32 frags = 128 regs/thread) are loaded ONCE
// into registers before the t-loop — zero U smem traffic per step. Per-warp
// producer flags: warp w publishes its 2 h-rows right after its epilogue.
__global__ void __launch_bounds__(256, 1) rnn_mma(float* __restrict__ out,
                                                  const float* __restrict__ Ub,
                                                  const float* __restrict__ bias) {
    extern __shared__ char sm[];
    __nv_bfloat16* s_uhi = (__nv_bfloat16*)sm;             // [32][ULD] (init only)
    __nv_bfloat16* s_ulo = s_uhi + U_ELEMS;
    __nv_bfloat16* s_hhi = s_ulo + U_ELEMS;                // [16][ULD]
    __nv_bfloat16* s_hlo = s_hhi + H_ELEMS;
    float* s_red = (float*)(s_hlo + H_ELEMS);              // [8 warps][2 nfrag][16][16]
    float* s_wx  = s_red + 8 * 512;                        // [2][16][32]

    const int tid = threadIdx.x, warp = tid >> 5, lane = tid & 31;
    const int ni = blockIdx.x >> 2, bi = blockIdx.x & 3;
    const int n0 = ni * 32, b0 = bi * 16;

    // ---- stage U slice once, load fragments into registers, then U smem is dead ----
    {
        uint32_t duh = smem_u32(s_uhi), dul = smem_u32(s_ulo);
        for (int i = tid; i < 32 * 128; i += 256) {
            int r = i >> 7, c = i & 127;
            cp_async16(duh + (r * ULD + c * 8) * 2, g_uhi + (size_t)(n0 + r) * D + c * 8);
            cp_async16(dul + (r * ULD + c * 8) * 2, g_ulo + (size_t)(n0 + r) * D + c * 8);
        }
        CP_COMMIT();
        asm volatile("cp.async.wait_group 0;" ::: "memory");
        __syncthreads();
    }

    const int kc0 = warp * 128;

    // register-pinned U fragments: [ks][j], hi and lo (32 frags x 4 regs = 128 regs)
    wmma::fragment<wmma::matrix_b, 16, 16, 16, __nv_bfloat16, wmma::col_major> pbh[8][2], pbl[8][2];
    #pragma unroll
    for (int ks = 0; ks < 8; ++ks) {
        const int kg = kc0 + ks * 16;
        #pragma unroll
        for (int j = 0; j < 2; ++j) {
            wmma::load_matrix_sync(pbh[ks][j], s_uhi + (size_t)(j * 16) * ULD + kg, ULD);
            wmma::load_matrix_sync(pbl[ks][j], s_ulo + (size_t)(j * 16) * ULD + kg, ULD);
        }
    }

    const uint32_t shh = smem_u32(s_hhi), shl = smem_u32(s_hlo);
    const uint32_t swx = smem_u32(s_wx);

    // this warp's 32 producer-warp flags: one per lane
    volatile unsigned* myflag = &g_flags[bi][(warp << 2) + (lane >> 3)][lane & 7][0];

    // ---- wx prefetch geometry: threads 0..127 move one 16B chunk each ----
    const int pr = tid >> 3, pc = tid & 7;
    const float* wx_src0 = out + (size_t)(b0 + pr) * (T * D) + n0 + pc * 4;
    const uint32_t wx_doff = (pr * 32 + pc * 4) * 4;

    // ---- epilogue constants ----
    const int eb  = tid >> 4;
    const int enl = (tid & 15) * 2;
    float2 cconst;
    cconst.x = Ub[n0 + enl]     + bias[n0 + enl];
    cconst.y = Ub[n0 + enl + 1] + bias[n0 + enl + 1];
    const size_t obase = (size_t)(b0 + eb) * (T * D) + n0 + enl;
    const int    hbase = (b0 + eb) * D + n0 + enl;
    const int    efr   = enl >> 4;
    const int    ec    = enl & 15;

    // ---- prologue: prefetch wx[0] ----
    if (tid < 128) cp_async16(swx + wx_doff, wx_src0);
    CP_COMMIT();

    for (int t = 0; t < T; ++t) {
        const __nv_bfloat16* Hhi = g_hhi[t & 1];
        const __nv_bfloat16* Hlo = g_hlo[t & 1];

        // ---- wait for this warp's 32 producer warps (no-op at t=0) ----
        while (*myflag < (unsigned)t) { }
        __syncwarp();

        // ---- self-stage this warp's h slab: 16 rows x 128 k, hi+lo ----
        #pragma unroll
        for (int j = 0; j < 8; ++j) {
            int i = lane + j * 32;
            int r = i >> 4, c = i & 15;
            uint32_t off = (r * ULD + kc0 + c * 8) * 2;
            const size_t goff = (size_t)(b0 + r) * D + kc0 + c * 8;
            cp_async16(shh + off, Hhi + goff);
            cp_async16(shl + off, Hlo + goff);
        }
        CP_COMMIT();

        // ---- prefetch wx[t+1] into the other smem buffer (overlaps compute) ----
        if (t + 1 < T && tid < 128)
            cp_async16(swx + ((t + 1) & 1) * 2048 + wx_doff, wx_src0 + (size_t)(t + 1) * D);
        CP_COMMIT();

        // completes h[t] and wx[t]; wx[t+1] may still fly
        asm volatile("cp.async.wait_group 1;" ::: "memory");
        __syncwarp();

        // ---- compute: M=16(b) x N=32 x K=128, 3 products, U from registers ----
        wmma::fragment<wmma::accumulator, 16, 16, 16, float> acc[2];
        wmma::fill_fragment(acc[0], 0.f);
        wmma::fill_fragment(acc[1], 0.f);
        #pragma unroll
        for (int ks = 0; ks < 8; ++ks) {
            const int kg = kc0 + ks * 16;
            wmma::fragment<wmma::matrix_a, 16, 16, 16, __nv_bfloat16, wmma::row_major> ah, al;
            wmma::load_matrix_sync(ah, s_hhi + kg, ULD);
            wmma::load_matrix_sync(al, s_hlo + kg, ULD);
            #pragma unroll
            for (int j = 0; j < 2; ++j) {
                wmma::mma_sync(acc[j], ah, pbh[ks][j], acc[j]);
                wmma::mma_sync(acc[j], al, pbh[ks][j], acc[j]);
                wmma::mma_sync(acc[j], ah, pbl[ks][j], acc[j]);
            }
        }
        wmma::store_matrix_sync(s_red + warp * 512,       acc[0], 16, wmma::mem_row_major);
        wmma::store_matrix_sync(s_red + warp * 512 + 256, acc[1], 16, wmma::mem_row_major);
        __syncthreads();

        // ---- 8-way K reduction + fused epilogue (wx from smem) ----
        {
            const float* p = s_red + efr * 256 + eb * 16 + ec;
            float s0 = 0.f, s1 = 0.f;
            #pragma unroll
            for (int w = 0; w < 8; ++w) { s0 += p[w * 512]; s1 += p[w * 512 + 1]; }
            const float* wxp = s_wx + (t & 1) * 512 + eb * 32 + enl;
            float zx = tanhf(wxp[0] + s0 + cconst.x);
            float zy = tanhf(wxp[1] + s1 + cconst.y);
            *(float2*)(out + obase + (size_t)t * D) = make_float2(zx, zy);
            if (t == T - 1)   // fused copy_hx: hx[b, n] = h_T
                *(float2*)(out + (size_t)B * T * D + hbase) = make_float2(zx, zy);

            __nv_bfloat16 hx = __float2bfloat16(zx), hy = __float2bfloat16(zy);
            *(__nv_bfloat162*)(g_hhi[(t + 1) & 1] + hbase) = __nv_bfloat162(hx, hy);
            *(__nv_bfloat162*)(g_hlo[(t + 1) & 1] + hbase) =
                __nv_bfloat162(__float2bfloat16(zx - __bfloat162float(hx)),
                               __float2bfloat16(zy - __bfloat162float(hy)));
        }

        // ---- per-warp early publish: this warp's 2 h-rows are ready ----
        __syncwarp();
        if (lane == 0) {
            __threadfence();
            *(volatile unsigned*)&g_flags[bi][ni][warp][0] = (unsigned)(t + 1);
        }
        __syncthreads();   // protects s_red / s_wx reuse next step
    }
}

extern "C" void kernel_launch(void* const* d_in, const int* in_sizes, int n_in,
                              void* d_out, int out_size) {
    const float* x    = (const float*)d_in[0];
    const float* Ww   = (const float*)d_in[1];
    const float* Wb   = (const float*)d_in[2];
    const float* Uw   = (const float*)d_in[3];
    const float* Ub   = (const float*)d_in[4];
    const float* bias = (const float*)d_in[5];
    float* out = (float*)d_out;

    cudaFuncSetAttribute(gemm_wx_mma, cudaFuncAttributeMaxDynamicSharedMemorySize, GEMM_SMEM);
    cudaFuncSetAttribute(rnn_mma,     cudaFuncAttributeMaxDynamicSharedMemorySize, RNN_SMEM);

    zero_h0<<<(B * D + 255) / 256, 256>>>();
    split_x<<<((size_t)B * T * D / 4) / 256, 256>>>(x);
    split_w<<<(D * D / 4) / 256, 256>>>(Ww);
    split_U<<<(D * D / 4) / 256, 256>>>(Uw);
    gemm_wx_mma<<<dim3(D / BN, (B * T) / BM), 256, GEMM_SMEM>>>(out, Wb);
    rnn_mma<<<RBLK, 256, RNN_SMEM>>>(out, Ub, bias);
}

// round 11
// speedup vs baseline: 2.0562x; 1.0030x over previous
#include <cuda_runtime.h>
#include <cuda_bf16.h>
#include <mma.h>
#include <math.h>
#include <stdint.h>

using namespace nvcuda;

#define B 64
#define T 512
#define D 1024
#define RBLK 128          // recurrence grid: 32 n-splits x 4 b-splits

// ---------------- wx GEMM config (K-concat hi/lo trick, K'=3072) ----------------
#define KK 3072
#define BM 128
#define BN 128
#define BK 32
#define NK (KK / BK)
#define LDT 40
#define STAGE_A (BM * LDT * 2)
#define AB_STAGES 3
#define SMEM_B_OFF (AB_STAGES * STAGE_A)
#define SMEM_BIAS_OFF (2 * AB_STAGES * STAGE_A)
#define GEMM_SMEM (SMEM_BIAS_OFF + 16 * BN * 4)

// ---------------- recurrence smem config ----------------
#define ULD 1032                               // padded k-stride (bf16 elems)
#define U_ELEMS (32 * ULD)                     // 32 n-rows x 1032
#define H_ELEMS (16 * ULD)                     // 16 b-rows x 1032
#define U_REGION (2 * U_ELEMS * 2)             // 132096 B; dead after frag pinning
// layout: [U region (aliased: s_red[2][8][512] | s_wx[3][512])] | s_hhi | s_hlo
#define RNN_SMEM (U_REGION + 2 * H_ELEMS * 2)  // 198144 B

// ---------------- scratch ----------------
__device__ unsigned g_flags[4][32][8][8];              // per-(bi,ni,warp) step flags, 32B padded
__device__ __nv_bfloat16 g_xs[(size_t)B * T * KK];     // x split K-concat [hi|lo|hi]
__device__ __nv_bfloat16 g_ws[(size_t)D * KK];         // W split K-concat [hi|hi|lo]
__device__ __nv_bfloat16 g_hhi[2][B * D];              // h hi, double buffered
__device__ __nv_bfloat16 g_hlo[2][B * D];              // h lo
__device__ __nv_bfloat16 g_uhi[D * D];                 // U hi, row-major [n][k]
__device__ __nv_bfloat16 g_ulo[D * D];                 // U lo

// ---------------- helpers ----------------
__device__ __forceinline__ uint32_t smem_u32(const void* p) {
    uint32_t a;
    asm("{ .reg .u64 t; cvta.to.shared.u64 t, %1; cvt.u32.u64 %0, t; }" : "=r"(a) : "l"(p));
    return a;
}
__device__ __forceinline__ void cp_async16(uint32_t dst, const void* src) {
    asm volatile("cp.async.cg.shared.global [%0], [%1], 16;" :: "r"(dst), "l"(src) : "memory");
}
#define CP_COMMIT() asm volatile("cp.async.commit_group;" ::: "memory")

// ---------------- init: zero h0 and the exchange flags ----------------
__global__ void zero_h0() {
    int i = blockIdx.x * blockDim.x + threadIdx.x;
    if (i < B * D) {
        g_hhi[0][i] = __nv_bfloat16(0.f);
        g_hlo[0][i] = __nv_bfloat16(0.f);
    }
    if (i < 4 * 32 * 8) g_flags[i >> 8][(i >> 3) & 31][i & 7][0] = 0;
}

// ---------------- fp32 -> bf16 splits ----------------
__global__ void split_x(const float* __restrict__ s) {
    size_t i = (size_t)blockIdx.x * blockDim.x + threadIdx.x;
    float4 v = ((const float4*)s)[i];
    size_t e = i * 4;
    size_t m = e >> 10;
    int    k = (int)(e & 1023);
    __nv_bfloat16 hx = __float2bfloat16(v.x), hy = __float2bfloat16(v.y);
    __nv_bfloat16 hz = __float2bfloat16(v.z), hw = __float2bfloat16(v.w);
    __nv_bfloat162 h01(hx, hy), h23(hz, hw);
    __nv_bfloat162 l01(__float2bfloat16(v.x - __bfloat162float(hx)),
                       __float2bfloat16(v.y - __bfloat162float(hy)));
    __nv_bfloat162 l23(__float2bfloat16(v.z - __bfloat162float(hz)),
                       __float2bfloat16(v.w - __bfloat162float(hw)));
    __nv_bfloat16* row = g_xs + m * KK;
    *(__nv_bfloat162*)(row + k)       = h01;  *(__nv_bfloat162*)(row + k + 2)       = h23;
    *(__nv_bfloat162*)(row + D + k)   = l01;  *(__nv_bfloat162*)(row + D + k + 2)   = l23;
    *(__nv_bfloat162*)(row + 2*D + k) = h01;  *(__nv_bfloat162*)(row + 2*D + k + 2) = h23;
}
__global__ void split_w(const float* __restrict__ s) {
    size_t i = (size_t)blockIdx.x * blockDim.x + threadIdx.x;
    float4 v = ((const float4*)s)[i];
    size_t e = i * 4;
    size_t n = e >> 10;
    int    k = (int)(e & 1023);
    __nv_bfloat16 hx = __float2bfloat16(v.x), hy = __float2bfloat16(v.y);
    __nv_bfloat16 hz = __float2bfloat16(v.z), hw = __float2bfloat16(v.w);
    __nv_bfloat162 h01(hx, hy), h23(hz, hw);
    __nv_bfloat162 l01(__float2bfloat16(v.x - __bfloat162float(hx)),
                       __float2bfloat16(v.y - __bfloat162float(hy)));
    __nv_bfloat162 l23(__float2bfloat16(v.z - __bfloat162float(hz)),
                       __float2bfloat16(v.w - __bfloat162float(hw)));
    __nv_bfloat16* row = g_ws + n * KK;
    *(__nv_bfloat162*)(row + k)       = h01;  *(__nv_bfloat162*)(row + k + 2)       = h23;
    *(__nv_bfloat162*)(row + D + k)   = h01;  *(__nv_bfloat162*)(row + D + k + 2)   = h23;
    *(__nv_bfloat162*)(row + 2*D + k) = l01;  *(__nv_bfloat162*)(row + 2*D + k + 2) = l23;
}
__global__ void split_U(const float* __restrict__ s) {
    size_t i = (size_t)blockIdx.x * blockDim.x + threadIdx.x;
    float4 v = ((const float4*)s)[i];
    __nv_bfloat16 hx = __float2bfloat16(v.x), hy = __float2bfloat16(v.y);
    __nv_bfloat16 hz = __float2bfloat16(v.z), hw = __float2bfloat16(v.w);
    ((__nv_bfloat162*)g_uhi)[2*i]   = __nv_bfloat162(hx, hy);
    ((__nv_bfloat162*)g_uhi)[2*i+1] = __nv_bfloat162(hz, hw);
    ((__nv_bfloat162*)g_ulo)[2*i]   = __nv_bfloat162(__float2bfloat16(v.x - __bfloat162float(hx)),
                                                     __float2bfloat16(v.y - __bfloat162float(hy)));
    ((__nv_bfloat162*)g_ulo)[2*i+1] = __nv_bfloat162(__float2bfloat16(v.z - __bfloat162float(hz)),
                                                     __float2bfloat16(v.w - __bfloat162float(hw)));
}

// ================= wx = x @ W^T + Wb via wmma (unchanged, proven) =================
__device__ __forceinline__ void fill_stage(uint32_t sb, int s, int m0, int n0, int k0, int tid) {
    uint32_t sa = sb + s * STAGE_A;
    uint32_t sbb = sb + SMEM_B_OFF + s * STAGE_A;
    #pragma unroll
    for (int j = 0; j < 2; ++j) {
        int idx = tid + j * 256;
        int r = idx >> 2, c = idx & 3;
        cp_async16(sa + r * (LDT * 2) + c * 16, g_xs + (size_t)(m0 + r) * KK + k0 + c * 8);
    }
    #pragma unroll
    for (int j = 0; j < 2; ++j) {
        int idx = tid + j * 256;
        int r = idx >> 2, c = idx & 3;
        cp_async16(sbb + r * (LDT * 2) + c * 16, g_ws + (size_t)(n0 + r) * KK + k0 + c * 8);
    }
    CP_COMMIT();
}

__global__ void __launch_bounds__(256) gemm_wx_mma(float* __restrict__ out,
                                                   const float* __restrict__ Wb) {
    extern __shared__ char smem[];
    uint32_t sb = smem_u32(smem);
    float* biasT = (float*)(smem + SMEM_BIAS_OFF);
    const int tid = threadIdx.x, warp = tid >> 5;
    const int wm = warp & 3, wn = warp >> 2;
    const int n0 = blockIdx.x * BN, m0 = blockIdx.y * BM;

    for (int i = tid; i < 16 * BN; i += 256) biasT[i] = Wb[n0 + (i & (BN - 1))];
    __syncthreads();

    wmma::fragment<wmma::accumulator, 16, 16, 16, float> c[2][4];
    #pragma unroll
    for (int i = 0; i < 2; ++i)
        #pragma unroll
        for (int j = 0; j < 4; ++j)
            wmma::load_matrix_sync(c[i][j], biasT + wn * 64 + j * 16, BN, wmma::mem_row_major);

    fill_stage(sb, 0, m0, n0, 0, tid);
    fill_stage(sb, 1, m0, n0, BK, tid);

    int rs = 0, ws = 2;
    for (int ks = 0; ks < NK; ++ks) {
        asm volatile("cp.async.wait_group 1;" ::: "memory");
        __syncthreads();

        const __nv_bfloat16* As = (const __nv_bfloat16*)(smem + rs * STAGE_A);
        const __nv_bfloat16* Bs = (const __nv_bfloat16*)(smem + SMEM_B_OFF + rs * STAGE_A);
        #pragma unroll
        for (int kk = 0; kk < 2; ++kk) {
            wmma::fragment<wmma::matrix_a, 16, 16, 16, __nv_bfloat16, wmma::row_major> a[2];
            wmma::fragment<wmma::matrix_b, 16, 16, 16, __nv_bfloat16, wmma::col_major> b[4];
            #pragma unroll
            for (int i = 0; i < 2; ++i)
                wmma::load_matrix_sync(a[i], As + (wm * 32 + i * 16) * LDT + kk * 16, LDT);
            #pragma unroll
            for (int j = 0; j < 4; ++j)
                wmma::load_matrix_sync(b[j], Bs + (wn * 64 + j * 16) * LDT + kk * 16, LDT);
            #pragma unroll
            for (int i = 0; i < 2; ++i)
                #pragma unroll
                for (int j = 0; j < 4; ++j)
                    wmma::mma_sync(c[i][j], a[i], b[j], c[i][j]);
        }

        if (ks + 2 < NK) fill_stage(sb, ws, m0, n0, (ks + 2) * BK, tid);
        else CP_COMMIT();
        rs = (rs == 2) ? 0 : rs + 1;
        ws = (ws == 2) ? 0 : ws + 1;
    }

    #pragma unroll
    for (int i = 0; i < 2; ++i)
        #pragma unroll
        for (int j = 0; j < 4; ++j)
            wmma::store_matrix_sync(out + (size_t)(m0 + wm * 32 + i * 16) * D + n0 + wn * 64 + j * 16,
                                    c[i][j], D, wmma::mem_row_major);
}

// ================= persistent HMMA recurrence: 1 sync/step, release flags =================
// 128 blocks x 256 threads. Block (ni, bi): n-cols [ni*32,+32), batches [bi*16,+16).
// U pinned in registers. Dead U smem region aliased as double-buffered s_red +
// triple-buffered s_wx. One __syncthreads per step (pre-reduction); it transitively
// orders all 32 blocks' epilogues, making the h double-buffer reuse race-free.
// Flag publish via st.release.gpu right after the h stores, before the out store.
__global__ void __launch_bounds__(256, 1) rnn_mma(float* __restrict__ out,
                                                  const float* __restrict__ Ub,
                                                  const float* __restrict__ bias) {
    extern __shared__ char sm[];
    __nv_bfloat16* s_uhi = (__nv_bfloat16*)sm;             // [32][ULD] (init only)
    __nv_bfloat16* s_ulo = s_uhi + U_ELEMS;
    __nv_bfloat16* s_hhi = (__nv_bfloat16*)(sm + U_REGION); // [16][ULD], warp-private slabs
    __nv_bfloat16* s_hlo = s_hhi + H_ELEMS;
    float* s_red = (float*)sm;                             // ALIAS of U region: [2][8][512]
    float* s_wx  = s_red + 2 * 8 * 512;                    // [3][512]

    const int tid = threadIdx.x, warp = tid >> 5, lane = tid & 31;
    const int ni = blockIdx.x >> 2, bi = blockIdx.x & 3;
    const int n0 = ni * 32, b0 = bi * 16;

    // ---- stage U slice once ----
    {
        uint32_t duh = smem_u32(s_uhi), dul = smem_u32(s_ulo);
        for (int i = tid; i < 32 * 128; i += 256) {
            int r = i >> 7, c = i & 127;
            cp_async16(duh + (r * ULD + c * 8) * 2, g_uhi + (size_t)(n0 + r) * D + c * 8);
            cp_async16(dul + (r * ULD + c * 8) * 2, g_ulo + (size_t)(n0 + r) * D + c * 8);
        }
        CP_COMMIT();
        asm volatile("cp.async.wait_group 0;" ::: "memory");
        __syncthreads();
    }

    const int kc0 = warp * 128;

    // register-pinned U fragments (loaded before the alias region is written)
    wmma::fragment<wmma::matrix_b, 16, 16, 16, __nv_bfloat16, wmma::col_major> pbh[8][2], pbl[8][2];
    #pragma unroll
    for (int ks = 0; ks < 8; ++ks) {
        const int kg = kc0 + ks * 16;
        #pragma unroll
        for (int j = 0; j < 2; ++j) {
            wmma::load_matrix_sync(pbh[ks][j], s_uhi + (size_t)(j * 16) * ULD + kg, ULD);
            wmma::load_matrix_sync(pbl[ks][j], s_ulo + (size_t)(j * 16) * ULD + kg, ULD);
        }
    }
    __syncthreads();   // all frag loads done -> U smem region may be reused (s_red/s_wx)

    const uint32_t shh = smem_u32(s_hhi), shl = smem_u32(s_hlo);
    const uint32_t swx = smem_u32(s_wx);

    // this warp's 32 producer-warp flags: one per lane
    unsigned* myflag = &g_flags[bi][(warp << 2) + (lane >> 3)][lane & 7][0];
    unsigned* pubflag = &g_flags[bi][ni][warp][0];

    // ---- wx prefetch geometry: threads 0..127 move one 16B chunk each ----
    const int pr = tid >> 3, pc = tid & 7;
    const float* wx_src0 = out + (size_t)(b0 + pr) * (T * D) + n0 + pc * 4;
    const uint32_t wx_doff = (pr * 32 + pc * 4) * 4;

    // ---- epilogue constants ----
    const int eb  = tid >> 4;
    const int enl = (tid & 15) * 2;
    float2 cconst;
    cconst.x = Ub[n0 + enl]     + bias[n0 + enl];
    cconst.y = Ub[n0 + enl + 1] + bias[n0 + enl + 1];
    const size_t obase = (size_t)(b0 + eb) * (T * D) + n0 + enl;
    const int    hbase = (b0 + eb) * D + n0 + enl;
    const int    efr   = enl >> 4;
    const int    ec    = enl & 15;

    // ---- prologue: prefetch wx[0] into wx buffer 0 ----
    if (tid < 128) cp_async16(swx + wx_doff, wx_src0);
    CP_COMMIT();

    int wb = 0;                                   // t % 3
    for (int t = 0; t < T; ++t) {
        const __nv_bfloat16* Hhi = g_hhi[t & 1];
        const __nv_bfloat16* Hlo = g_hlo[t & 1];
        const int nwb = (wb == 2) ? 0 : wb + 1;   // (t+1) % 3

        // ---- acquire-poll this warp's 32 producer warps (no-op at t=0) ----
        {
            unsigned v;
            do {
                asm volatile("ld.acquire.gpu.global.u32 %0, [%1];" : "=r"(v) : "l"(myflag) : "memory");
            } while (v < (unsigned)t);
        }
        __syncwarp();

        // ---- self-stage this warp's h slab (warp-private smem region) ----
        #pragma unroll
        for (int j = 0; j < 8; ++j) {
            int i = lane + j * 32;
            int r = i >> 4, c = i & 15;
            uint32_t off = (r * ULD + kc0 + c * 8) * 2;
            const size_t goff = (size_t)(b0 + r) * D + kc0 + c * 8;
            cp_async16(shh + off, Hhi + goff);
            cp_async16(shl + off, Hlo + goff);
        }
        CP_COMMIT();

        // ---- prefetch wx[t+1] into buffer (t+1)%3 ----
        if (t + 1 < T && tid < 128)
            cp_async16(swx + nwb * 2048 + wx_doff, wx_src0 + (size_t)(t + 1) * D);
        CP_COMMIT();

        // completes h[t] and wx[t]; wx[t+1] may still fly
        asm volatile("cp.async.wait_group 1;" ::: "memory");
        __syncwarp();

        // ---- compute: M=16(b) x N=32 x K=128, 3 products, U from registers ----
        wmma::fragment<wmma::accumulator, 16, 16, 16, float> acc[2];
        wmma::fill_fragment(acc[0], 0.f);
        wmma::fill_fragment(acc[1], 0.f);
        #pragma unroll
        for (int ks = 0; ks < 8; ++ks) {
            const int kg = kc0 + ks * 16;
            wmma::fragment<wmma::matrix_a, 16, 16, 16, __nv_bfloat16, wmma::row_major> ah, al;
            wmma::load_matrix_sync(ah, s_hhi + kg, ULD);
            wmma::load_matrix_sync(al, s_hlo + kg, ULD);
            #pragma unroll
            for (int j = 0; j < 2; ++j) {
                wmma::mma_sync(acc[j], ah, pbh[ks][j], acc[j]);
                wmma::mma_sync(acc[j], al, pbh[ks][j], acc[j]);
                wmma::mma_sync(acc[j], ah, pbl[ks][j], acc[j]);
            }
        }
        float* red = s_red + (t & 1) * 4096;
        wmma::store_matrix_sync(red + warp * 512,       acc[0], 16, wmma::mem_row_major);
        wmma::store_matrix_sync(red + warp * 512 + 256, acc[1], 16, wmma::mem_row_major);
        __syncthreads();   // the ONE block sync per step

        // ---- 8-way K reduction + epilogue: h stores -> flag -> out store ----
        {
            const float* p = red + efr * 256 + eb * 16 + ec;
            float s0 = 0.f, s1 = 0.f;
            #pragma unroll
            for (int w = 0; w < 8; ++w) { s0 += p[w * 512]; s1 += p[w * 512 + 1]; }
            const float* wxp = s_wx + wb * 512 + eb * 32 + enl;
            float zx = tanhf(wxp[0] + s0 + cconst.x);
            float zy = tanhf(wxp[1] + s1 + cconst.y);

            // h stores FIRST (these are what consumers need)
            __nv_bfloat16 hx = __float2bfloat16(zx), hy = __float2bfloat16(zy);
            *(__nv_bfloat162*)(g_hhi[(t + 1) & 1] + hbase) = __nv_bfloat162(hx, hy);
            *(__nv_bfloat162*)(g_hlo[(t + 1) & 1] + hbase) =
                __nv_bfloat162(__float2bfloat16(zx - __bfloat162float(hx)),
                               __float2bfloat16(zy - __bfloat162float(hy)));
            __syncwarp();
            if (lane == 0)
                asm volatile("st.release.gpu.global.u32 [%0], %1;"
                             :: "l"(pubflag), "r"((unsigned)(t + 1)) : "memory");

            // out store off the critical path
            *(float2*)(out + obase + (size_t)t * D) = make_float2(zx, zy);
            if (t == T - 1)   // fused copy_hx
                *(float2*)(out + (size_t)B * T * D + hbase) = make_float2(zx, zy);
        }
        wb = nwb;
    }
}

extern "C" void kernel_launch(void* const* d_in, const int* in_sizes, int n_in,
                              void* d_out, int out_size) {
    const float* x    = (const float*)d_in[0];
    const float* Ww   = (const float*)d_in[1];
    const float* Wb   = (const float*)d_in[2];
    const float* Uw   = (const float*)d_in[3];
    const float* Ub   = (const float*)d_in[4];
    const float* bias = (const float*)d_in[5];
    float* out = (float*)d_out;

    cudaFuncSetAttribute(gemm_wx_mma, cudaFuncAttributeMaxDynamicSharedMemorySize, GEMM_SMEM);
    cudaFuncSetAttribute(rnn_mma,     cudaFuncAttributeMaxDynamicSharedMemorySize, RNN_SMEM);

    zero_h0<<<(B * D + 255) / 256, 256>>>();
    split_x<<<((size_t)B * T * D / 4) / 256, 256>>>(x);
    split_w<<<(D * D / 4) / 256, 256>>>(Ww);
    split_U<<<(D * D / 4) / 256, 256>>>(Uw);
    gemm_wx_mma<<<dim3(D / BN, (B * T) / BM), 256, GEMM_SMEM>>>(out, Wb);
    rnn_mma<<<RBLK, 256, RNN_SMEM>>>(out, Ub, bias);
}